// round 7
// baseline (speedup 1.0000x reference)
#include <cuda_runtime.h>
#include <cuda_bf16.h>
#include <cstdint>
#include <stdint.h>
#include <math.h>

#define NN 2000
#define BB 8
#define LL 12
#define DD 2
#define HH 64
#define EE 16000
#define ETOT 18000
#define NSEQ (NN*BB)                 // 16000
#define OUT1_ELEMS (NSEQ*LL*HH)      // 12,288,000

__device__ float g_out1[OUT1_ELEMS];
__device__ float g_agg[OUT1_ELEMS];

// ---------------------------------------------------------------------------
// FMA-only fast math (no MUFU)
// ---------------------------------------------------------------------------
__device__ __forceinline__ float fexp2(float y) {
    y = fminf(fmaxf(y, -125.0f), 125.0f);
    float r = __fadd_rn(y, 12582912.0f);
    int   n = __float_as_int(r) - 0x4B400000;
    float f = __fsub_rn(y, __fsub_rn(r, 12582912.0f));
    float u = f * 0.69314718055994531f;
    float p = fmaf(u, 1.3888889e-3f, 8.3333333e-3f);
    p = fmaf(u, p, 4.1666667e-2f);
    p = fmaf(u, p, 1.6666667e-1f);
    p = fmaf(u, p, 0.5f);
    p = fmaf(u, p, 1.0f);
    p = fmaf(u, p, 1.0f);
    return p * __int_as_float((n + 127) << 23);
}
__device__ __forceinline__ float frcp(float x) {
    float r = __int_as_float(0x7EF311C3 - __float_as_int(x));
    r = r * __fmaf_rn(-x, r, 2.0f);
    r = r * __fmaf_rn(-x, r, 2.0f);
    r = r * __fmaf_rn(-x, r, 2.0f);
    return r;
}
__device__ __forceinline__ float fsig(float x) {
    return frcp(1.0f + fexp2(-1.4426950408889634f * x));
}
__device__ __forceinline__ float ftanh(float x) {
    float e = fexp2(2.8853900817779268f * x);
    return fmaf(-2.0f, frcp(1.0f + e), 1.0f);
}

// ---------------------------------------------------------------------------
// mma.sync / ldmatrix helpers (family-portable: sm_80+, works on sm_103)
// ---------------------------------------------------------------------------
__device__ __forceinline__ uint32_t smem_u32(const void* p) {
    uint32_t a;
    asm("{ .reg .u64 t; cvta.to.shared.u64 t, %1; cvt.u32.u64 %0, t; }"
        : "=r"(a) : "l"(p));
    return a;
}
__device__ __forceinline__ void ldmx4(uint32_t* r, uint32_t addr) {
    asm volatile("ldmatrix.sync.aligned.m8n8.x4.shared.b16 {%0,%1,%2,%3}, [%4];"
                 : "=r"(r[0]), "=r"(r[1]), "=r"(r[2]), "=r"(r[3]) : "r"(addr));
}
__device__ __forceinline__ void mma16816(float* d, const uint32_t* a, const uint32_t* b) {
    asm volatile("mma.sync.aligned.m16n8k16.row.col.f32.bf16.bf16.f32 "
                 "{%0,%1,%2,%3}, {%4,%5,%6,%7}, {%8,%9}, {%0,%1,%2,%3};"
                 : "+f"(d[0]), "+f"(d[1]), "+f"(d[2]), "+f"(d[3])
                 : "r"(a[0]), "r"(a[1]), "r"(a[2]), "r"(a[3]),
                   "r"(b[0]), "r"(b[1]));
}

// Swizzled tile addressing: row-major [rows][128 k] bf16, 16 16B-units/row,
// unit permuted by XOR with (row & 7)  -> conflict-free ldmatrix + stores.
__device__ __forceinline__ uint32_t tile_byte(int row, int k) {
    return (uint32_t)(row * 16 + (((k >> 3)) ^ (row & 7))) * 16u
         + (uint32_t)(k & 7) * 2u;
}

// ---------------------------------------------------------------------------
// GRU1 (unchanged)
// ---------------------------------------------------------------------------
extern "C" __global__ void gru1_kernel(const float* __restrict__ data,
                                       const float* __restrict__ Wih,
                                       const float* __restrict__ Whh,
                                       const float* __restrict__ bih,
                                       const float* __restrict__ bhh,
                                       float* __restrict__ h1_out)
{
    extern __shared__ float sm[];
    float* whhT = sm;
    float* h_sh = sm + 12352;
    float* x_sh = sm + 12352 + 1024;

    const int tid = threadIdx.x;
    const int grp = tid >> 6;
    const int j   = tid & 63;

    for (int idx = tid; idx < 12288; idx += 256) {
        int g = idx >> 6, k = idx & 63;
        int m = g >> 6, jj = g & 63;
        whhT[k * 193 + m * 64 + jj] = Whh[idx];
    }
    for (int idx = tid; idx < 384; idx += 256)
        x_sh[idx] = data[(size_t)blockIdx.x * 384 + idx];

    float wr0 = Wih[j * 2],        wr1 = Wih[j * 2 + 1];
    float wz0 = Wih[(64 + j) * 2], wz1 = Wih[(64 + j) * 2 + 1];
    float wn0 = Wih[(128 + j)* 2], wn1 = Wih[(128 + j)* 2 + 1];
    float br = bih[j], bz = bih[64 + j], bn = bih[128 + j];
    float cr = bhh[j], cz = bhh[64 + j], cn = bhh[128 + j];

    float h[4] = {0.f, 0.f, 0.f, 0.f};
    const int s0 = blockIdx.x * 16 + grp * 4;
    float* outb = g_out1 + (size_t)s0 * 768 + j;

    for (int l = 0; l < LL; l++) {
        *(float4*)&h_sh[grp * 256 + j * 4] = make_float4(h[0], h[1], h[2], h[3]);
        __syncthreads();

        float ghr[4], ghz[4], ghn[4];
        #pragma unroll
        for (int s = 0; s < 4; s++) { ghr[s] = cr; ghz[s] = cz; ghn[s] = cn; }

        const float* wp = whhT + j;
        const float* hp = h_sh + grp * 256;
        #pragma unroll 4
        for (int k = 0; k < 64; k++) {
            float w0 = wp[k * 193];
            float w1 = wp[k * 193 + 64];
            float w2 = wp[k * 193 + 128];
            float4 hv = *(const float4*)&hp[k * 4];
            ghr[0] = fmaf(hv.x, w0, ghr[0]); ghz[0] = fmaf(hv.x, w1, ghz[0]); ghn[0] = fmaf(hv.x, w2, ghn[0]);
            ghr[1] = fmaf(hv.y, w0, ghr[1]); ghz[1] = fmaf(hv.y, w1, ghz[1]); ghn[1] = fmaf(hv.y, w2, ghn[1]);
            ghr[2] = fmaf(hv.z, w0, ghr[2]); ghz[2] = fmaf(hv.z, w1, ghz[2]); ghn[2] = fmaf(hv.z, w2, ghn[2]);
            ghr[3] = fmaf(hv.w, w0, ghr[3]); ghz[3] = fmaf(hv.w, w1, ghz[3]); ghn[3] = fmaf(hv.w, w2, ghn[3]);
        }
        #pragma unroll
        for (int s = 0; s < 4; s++) {
            float x0 = x_sh[(grp * 4 + s) * 24 + l * 2];
            float x1 = x_sh[(grp * 4 + s) * 24 + l * 2 + 1];
            float gir = fmaf(x1, wr1, fmaf(x0, wr0, br));
            float giz = fmaf(x1, wz1, fmaf(x0, wz0, bz));
            float gin = fmaf(x1, wn1, fmaf(x0, wn0, bn));
            float r = fsig(gir + ghr[s]);
            float z = fsig(giz + ghz[s]);
            float n = ftanh(fmaf(r, ghn[s], gin));
            h[s] = fmaf(z, h[s] - n, n);
            outb[s * 768 + l * 64] = h[s];
        }
        __syncthreads();
    }
    #pragma unroll
    for (int s = 0; s < 4; s++)
        h1_out[(s0 + s) * 64 + j] = h[s];
}

// ---------------------------------------------------------------------------
extern "C" __global__ void zero_agg_kernel()
{
    for (int i = blockIdx.x * blockDim.x + threadIdx.x; i < OUT1_ELEMS;
         i += gridDim.x * blockDim.x)
        g_agg[i] = 0.0f;
}

// ---------------------------------------------------------------------------
// Edge kernel: warp-level mma.sync bf16 hi/lo split, M=96 N=64 K=128.
// smem byte map:
//   [0..1024)       misc (feats @64, hdn @576, hdn2 @640)
//   [1024..25600)   A_hi  (96 x 128 bf16, swizzled)
//   [25600..50176)  A_lo
//   [50176..66560)  B_hi  (64 x 128 bf16, swizzled)   <- alpha f32 overlays
//   [66560..82944)  B_lo
// ---------------------------------------------------------------------------
#define SM_AHI   1024
#define SM_ALO   25600
#define SM_BHI   50176
#define SM_BLO   66560
#define SM_ALPHA 50176
#define EDGE_SMEM_BYTES 82944

extern "C" __global__ void __launch_bounds__(256, 2)
edge_kernel(const float* __restrict__ features,
            const int* __restrict__ ei,
            const float* __restrict__ W1,
            const float* __restrict__ b1,
            const float* __restrict__ W2,
            const float* __restrict__ b2,
            const float* __restrict__ W3,
            const float* __restrict__ b3)
{
    extern __shared__ char smc[];
    const uint32_t smem_base = smem_u32(smc);
    float* feats = (float*)(smc + 64);
    float* hdn   = (float*)(smc + 576);
    float* hdn2  = (float*)(smc + 640);

    const int tid = threadIdx.x, wid = tid >> 5, lid = tid & 31;
    const int e = blockIdx.x;
    int src, dst;
    if (e < EE) { src = ei[e]; dst = ei[EE + e]; }
    else        { src = dst = e - EE; }

    if (tid < 128)
        feats[tid] = (tid < 64) ? features[dst * 64 + tid]
                                : features[src * 64 + (tid - 64)];

    // ---- load states, split bf16 hi/lo, store swizzled A tiles (96x128) ----
    {
        const float* pi = g_out1 + (size_t)dst * 6144;
        const float* pj = g_out1 + (size_t)src * 6144;
        for (int p = tid; p < 6144; p += 256) {
            int m = p >> 6, kp = p & 63, k = kp * 2;
            const float* sp = (kp < 32) ? (pi + m * 64 + k) : (pj + m * 64 + (k - 64));
            float2 v = *(const float2*)sp;
            __nv_bfloat16 hx = __float2bfloat16(v.x);
            __nv_bfloat16 hy = __float2bfloat16(v.y);
            __nv_bfloat16 lx = __float2bfloat16(v.x - __bfloat162float(hx));
            __nv_bfloat16 ly = __float2bfloat16(v.y - __bfloat162float(hy));
            uint32_t off = tile_byte(m, k);
            __nv_bfloat162 th; th.x = hx; th.y = hy;
            __nv_bfloat162 tl; tl.x = lx; tl.y = ly;
            *(__nv_bfloat162*)(smc + SM_AHI + off) = th;
            *(__nv_bfloat162*)(smc + SM_ALO + off) = tl;
        }
    }
    __syncthreads();

    // ---- tiny MLP -> (h0, h1) ----
    if (tid < 16) {
        float acc = b1[tid];
        const float* wrow = W1 + tid * 128;
        #pragma unroll 8
        for (int k = 0; k < 128; k++) acc = fmaf(feats[k], wrow[k], acc);
        hdn[tid] = fsig(acc);
    }
    __syncthreads();
    if (tid < 2) {
        float acc = b2[tid];
        const float* wrow = W2 + tid * 16;
        #pragma unroll
        for (int k = 0; k < 16; k++) acc = fmaf(hdn[k], wrow[k], acc);
        hdn2[tid] = fsig(acc);
    }
    __syncthreads();

    // ---- generate w, split hi/lo into B tiles (Bt[n][k] = w[k][n], 64x128) ----
    {
        const float h0 = hdn2[0], h1v = hdn2[1];
        const int n = tid & 63;
        const int kp0 = tid >> 6;
        #pragma unroll 4
        for (int i = 0; i < 16; i++) {
            int kp = kp0 + 4 * i;
            int k = kp * 2;
            float2 wa = ((const float2*)W3)[k * 64 + n];
            float2 wb = ((const float2*)W3)[(k + 1) * 64 + n];
            float w0 = fmaf(h0, wa.x, fmaf(h1v, wa.y, b3[k * 64 + n]));
            float w1 = fmaf(h0, wb.x, fmaf(h1v, wb.y, b3[(k + 1) * 64 + n]));
            __nv_bfloat16 hx = __float2bfloat16(w0);
            __nv_bfloat16 hy = __float2bfloat16(w1);
            __nv_bfloat16 lx = __float2bfloat16(w0 - __bfloat162float(hx));
            __nv_bfloat16 ly = __float2bfloat16(w1 - __bfloat162float(hy));
            uint32_t off = tile_byte(n, k);
            __nv_bfloat162 th; th.x = hx; th.y = hy;
            __nv_bfloat162 tl; tl.x = lx; tl.y = ly;
            *(__nv_bfloat162*)(smc + SM_BHI + off) = th;
            *(__nv_bfloat162*)(smc + SM_BLO + off) = tl;
        }
    }
    __syncthreads();

    // ---- warp MMA: 6 active warps, grid 3M x 2N; acc[2 mtile][4 ntile][4] ----
    float acc[2][4][4];
    #pragma unroll
    for (int a = 0; a < 2; a++)
        #pragma unroll
        for (int b = 0; b < 4; b++)
            #pragma unroll
            for (int c = 0; c < 4; c++) acc[a][b][c] = 0.0f;

    if (wid < 6) {
        const int mw = wid >> 1, nw = wid & 1;
        // ldmatrix lane address params
        const int ar    = (lid & 7) + ((lid >> 3) & 1) * 8;   // row within m16
        const int aku   = lid >> 4;                            // k-unit add (0/1)
        const int arow0 = mw * 32 + ar;
        const int arow1 = arow0 + 16;
        const uint32_t ab0 = (uint32_t)arow0 * 256u, ax0 = (uint32_t)(arow0 & 7);
        const uint32_t ab1 = (uint32_t)arow1 * 256u, ax1 = (uint32_t)(arow1 & 7);

        const int br    = (lid & 7) + ((lid >> 4) << 3);      // row within n16
        const int bku   = (lid >> 3) & 1;
        const int brow0 = nw * 32 + br;
        const int brow1 = brow0 + 16;
        const uint32_t bb0 = (uint32_t)brow0 * 256u, bx0 = (uint32_t)(brow0 & 7);
        const uint32_t bb1 = (uint32_t)brow1 * 256u, bx1 = (uint32_t)(brow1 & 7);

        #pragma unroll
        for (int sp = 0; sp < 3; sp++) {
            const uint32_t Ab = smem_base + (sp == 2 ? SM_ALO : SM_AHI);
            const uint32_t Bb = smem_base + (sp == 1 ? SM_BLO : SM_BHI);
            #pragma unroll
            for (int ks = 0; ks < 8; ks++) {
                const uint32_t kb = (uint32_t)(ks * 2);
                uint32_t af0[4], af1[4], bf0[4], bf1[4];
                ldmx4(af0, Ab + ab0 + (((kb + aku) ^ ax0) << 4));
                ldmx4(af1, Ab + ab1 + (((kb + aku) ^ ax1) << 4));
                ldmx4(bf0, Bb + bb0 + (((kb + bku) ^ bx0) << 4));
                ldmx4(bf1, Bb + bb1 + (((kb + bku) ^ bx1) << 4));
                mma16816(acc[0][0], af0, bf0);
                mma16816(acc[0][1], af0, bf0 + 2);
                mma16816(acc[0][2], af0, bf1);
                mma16816(acc[0][3], af0, bf1 + 2);
                mma16816(acc[1][0], af1, bf0);
                mma16816(acc[1][1], af1, bf0 + 2);
                mma16816(acc[1][2], af1, bf1);
                mma16816(acc[1][3], af1, bf1 + 2);
            }
        }
    }
    __syncthreads();   // B regions dead; alpha overlay safe

    // ---- leaky_relu + store alpha to swizzled smem [96][64] f32 ----
    if (wid < 6) {
        const int mw = wid >> 1, nw = wid & 1;
        float* al = (float*)(smc + SM_ALPHA);
        const int g = lid >> 2, c2 = (lid & 3) * 2;
        #pragma unroll
        for (int mt = 0; mt < 2; mt++) {
            const int r0 = mw * 32 + mt * 16 + g;
            const int r1 = r0 + 8;
            #pragma unroll
            for (int nt = 0; nt < 4; nt++) {
                const int c0 = nw * 32 + nt * 8 + c2;
                float v0 = acc[mt][nt][0], v1 = acc[mt][nt][1];
                float v2 = acc[mt][nt][2], v3 = acc[mt][nt][3];
                v0 = v0 > 0.f ? v0 : 0.01f * v0;
                v1 = v1 > 0.f ? v1 : 0.01f * v1;
                v2 = v2 > 0.f ? v2 : 0.01f * v2;
                v3 = v3 > 0.f ? v3 : 0.01f * v3;
                float2 p0; p0.x = v0; p0.y = v1;
                float2 p1; p1.x = v2; p1.y = v3;
                *(float2*)&al[r0 * 64 + 4 * ((c0 >> 2) ^ (r0 & 15)) + (c0 & 3)] = p0;
                *(float2*)&al[r1 * 64 + 4 * ((c0 >> 2) ^ (r1 & 15)) + (c0 & 3)] = p1;
            }
        }
    }
    __syncthreads();

    // ---- softmax over batch (8) + msg + vector atomic scatter ----
    if (tid < 192) {
        const int l = tid >> 4, h4 = tid & 15;
        const float* al = (const float*)(smc + SM_ALPHA);
        float4 a[8];
        float4 mx = make_float4(-1e30f, -1e30f, -1e30f, -1e30f);
        #pragma unroll
        for (int b = 0; b < 8; b++) {
            int m = b * 12 + l;
            a[b] = *(const float4*)&al[m * 64 + 4 * (h4 ^ (m & 15))];
            mx.x = fmaxf(mx.x, a[b].x); mx.y = fmaxf(mx.y, a[b].y);
            mx.z = fmaxf(mx.z, a[b].z); mx.w = fmaxf(mx.w, a[b].w);
        }
        float4 ssum = make_float4(0.f, 0.f, 0.f, 0.f);
        #pragma unroll
        for (int b = 0; b < 8; b++) {
            a[b].x = fexp2(1.4426950408889634f * (a[b].x - mx.x));
            a[b].y = fexp2(1.4426950408889634f * (a[b].y - mx.y));
            a[b].z = fexp2(1.4426950408889634f * (a[b].z - mx.z));
            a[b].w = fexp2(1.4426950408889634f * (a[b].w - mx.w));
            ssum.x += a[b].x; ssum.y += a[b].y; ssum.z += a[b].z; ssum.w += a[b].w;
        }
        float4 inv = make_float4(frcp(ssum.x), frcp(ssum.y), frcp(ssum.z), frcp(ssum.w));
        float* aggb = g_agg + (size_t)dst * 6144;
        #pragma unroll
        for (int b = 0; b < 8; b++) {
            int m = b * 12 + l;
            // reconstruct stj[m][4h4..4h4+3] = A_hi + A_lo at k = 64 + 4*h4
            int k = 64 + 4 * h4;
            uint32_t unit = (uint32_t)(m * 16 + ((k >> 3) ^ (m & 7))) * 16u
                          + (uint32_t)(k & 7) * 2u;
            __nv_bfloat162 h01 = *(const __nv_bfloat162*)(smc + SM_AHI + unit);
            __nv_bfloat162 h23 = *(const __nv_bfloat162*)(smc + SM_AHI + unit + 4);
            __nv_bfloat162 l01 = *(const __nv_bfloat162*)(smc + SM_ALO + unit);
            __nv_bfloat162 l23 = *(const __nv_bfloat162*)(smc + SM_ALO + unit + 4);
            float sj0 = __bfloat162float(h01.x) + __bfloat162float(l01.x);
            float sj1 = __bfloat162float(h01.y) + __bfloat162float(l01.y);
            float sj2 = __bfloat162float(h23.x) + __bfloat162float(l23.x);
            float sj3 = __bfloat162float(h23.y) + __bfloat162float(l23.y);
            float4 msg;
            msg.x = a[b].x * inv.x * sj0;
            msg.y = a[b].y * inv.y * sj1;
            msg.z = a[b].z * inv.z * sj2;
            msg.w = a[b].w * inv.w * sj3;
            asm volatile("red.global.add.v4.f32 [%0], {%1,%2,%3,%4};"
                         :: "l"(aggb + m * 64 + h4 * 4), "f"(msg.x), "f"(msg.y),
                            "f"(msg.z), "f"(msg.w) : "memory");
        }
    }
}

// ---------------------------------------------------------------------------
// GRU2 (unchanged)
// ---------------------------------------------------------------------------
extern "C" __global__ void gru2_kernel(const float* __restrict__ Wih,
                                       const float* __restrict__ Whh,
                                       const float* __restrict__ bih,
                                       const float* __restrict__ bhh,
                                       float* __restrict__ h2_out)
{
    extern __shared__ float sm[];
    float* wT   = sm;
    float* h_sh = sm + 24640;
    float* x_sh = sm + 24640 + 1024;

    const int tid = threadIdx.x;
    const int grp = tid >> 6;
    const int j   = tid & 63;

    for (int idx = tid; idx < 12288; idx += 256) {
        int g = idx >> 6, k = idx & 63;
        int m = g >> 6, jj = g & 63;
        wT[k * 385 + m * 64 + jj]       = Wih[idx];
        wT[k * 385 + 192 + m * 64 + jj] = Whh[idx];
    }

    float br = bih[j], bz = bih[64 + j], bn = bih[128 + j];
    float cr = bhh[j], cz = bhh[64 + j], cn = bhh[128 + j];

    float h[4] = {0.f, 0.f, 0.f, 0.f};
    const int s0 = blockIdx.x * 16 + grp * 4;
    const float* xg = g_agg + (size_t)s0 * 768 + j;

    for (int l = 0; l < LL; l++) {
        float4 xv;
        xv.x = fmaxf(xg[0 * 768 + l * 64], 0.0f);
        xv.y = fmaxf(xg[1 * 768 + l * 64], 0.0f);
        xv.z = fmaxf(xg[2 * 768 + l * 64], 0.0f);
        xv.w = fmaxf(xg[3 * 768 + l * 64], 0.0f);
        *(float4*)&x_sh[grp * 256 + j * 4] = xv;
        *(float4*)&h_sh[grp * 256 + j * 4] = make_float4(h[0], h[1], h[2], h[3]);
        __syncthreads();

        float gr[4], gz[4], gn[4];
        #pragma unroll
        for (int s = 0; s < 4; s++) { gr[s] = br + cr; gz[s] = bz + cz; gn[s] = bn; }
        float ghn[4] = {cn, cn, cn, cn};

        const float* wp = wT + j;
        const float* hp = h_sh + grp * 256;
        const float* xp = x_sh + grp * 256;
        #pragma unroll 2
        for (int k = 0; k < 64; k++) {
            float wi0 = wp[k * 385];
            float wi1 = wp[k * 385 + 64];
            float wi2 = wp[k * 385 + 128];
            float wh0 = wp[k * 385 + 192];
            float wh1 = wp[k * 385 + 256];
            float wh2 = wp[k * 385 + 320];
            float4 xk = *(const float4*)&xp[k * 4];
            float4 hk = *(const float4*)&hp[k * 4];
            gr[0] = fmaf(xk.x, wi0, gr[0]); gz[0] = fmaf(xk.x, wi1, gz[0]); gn[0] = fmaf(xk.x, wi2, gn[0]);
            gr[0] = fmaf(hk.x, wh0, gr[0]); gz[0] = fmaf(hk.x, wh1, gz[0]); ghn[0] = fmaf(hk.x, wh2, ghn[0]);
            gr[1] = fmaf(xk.y, wi0, gr[1]); gz[1] = fmaf(xk.y, wi1, gz[1]); gn[1] = fmaf(xk.y, wi2, gn[1]);
            gr[1] = fmaf(hk.y, wh0, gr[1]); gz[1] = fmaf(hk.y, wh1, gz[1]); ghn[1] = fmaf(hk.y, wh2, ghn[1]);
            gr[2] = fmaf(xk.z, wi0, gr[2]); gz[2] = fmaf(xk.z, wi1, gz[2]); gn[2] = fmaf(xk.z, wi2, gn[2]);
            gr[2] = fmaf(hk.z, wh0, gr[2]); gz[2] = fmaf(hk.z, wh1, gz[2]); ghn[2] = fmaf(hk.z, wh2, ghn[2]);
            gr[3] = fmaf(xk.w, wi0, gr[3]); gz[3] = fmaf(xk.w, wi1, gz[3]); gn[3] = fmaf(xk.w, wi2, gn[3]);
            gr[3] = fmaf(hk.w, wh0, gr[3]); gz[3] = fmaf(hk.w, wh1, gz[3]); ghn[3] = fmaf(hk.w, wh2, ghn[3]);
        }
        #pragma unroll
        for (int s = 0; s < 4; s++) {
            float r = fsig(gr[s]);
            float z = fsig(gz[s]);
            float n = ftanh(fmaf(r, ghn[s], gn[s]));
            h[s] = fmaf(z, h[s] - n, n);
        }
        __syncthreads();
    }
    #pragma unroll
    for (int s = 0; s < 4; s++)
        h2_out[(s0 + s) * 64 + j] = h[s];
}

// ---------------------------------------------------------------------------

static const int GRU1_SMEM = (12352 + 1024 + 384) * 4;
static const int GRU2_SMEM = (24640 + 1024 + 1024) * 4;

extern "C" void kernel_launch(void* const* d_in, const int* in_sizes, int n_in,
                              void* d_out, int out_size)
{
    const float* data     = (const float*)d_in[0];
    const float* features = (const float*)d_in[1];
    const int*   ei       = (const int*)  d_in[2];
    const float* Wih1     = (const float*)d_in[3];
    const float* Whh1     = (const float*)d_in[4];
    const float* bih1     = (const float*)d_in[5];
    const float* bhh1     = (const float*)d_in[6];
    const float* W1       = (const float*)d_in[7];
    const float* b1       = (const float*)d_in[8];
    const float* W2       = (const float*)d_in[9];
    const float* b2       = (const float*)d_in[10];
    const float* W3       = (const float*)d_in[11];
    const float* b3       = (const float*)d_in[12];
    const float* Wih2     = (const float*)d_in[13];
    const float* Whh2     = (const float*)d_in[14];
    const float* bih2     = (const float*)d_in[15];
    const float* bhh2     = (const float*)d_in[16];
    float* out = (float*)d_out;

    cudaFuncSetAttribute(gru1_kernel, cudaFuncAttributeMaxDynamicSharedMemorySize, GRU1_SMEM);
    cudaFuncSetAttribute(gru2_kernel, cudaFuncAttributeMaxDynamicSharedMemorySize, GRU2_SMEM);
    cudaFuncSetAttribute(edge_kernel, cudaFuncAttributeMaxDynamicSharedMemorySize, EDGE_SMEM_BYTES);

    gru1_kernel<<<NSEQ / 16, 256, GRU1_SMEM>>>(data, Wih1, Whh1, bih1, bhh1, out);
    zero_agg_kernel<<<2048, 256>>>();
    edge_kernel<<<ETOT, 256, EDGE_SMEM_BYTES>>>(features, ei, W1, b1, W2, b2, W3, b3);
    gru2_kernel<<<NSEQ / 16, 256, GRU2_SMEM>>>(Wih2, Whh2, bih2, bhh2, out + NSEQ * HH);
}

// round 9
// speedup vs baseline: 1.9223x; 1.9223x over previous
#include <cuda_runtime.h>
#include <cuda_bf16.h>
#include <cstdint>
#include <stdint.h>
#include <math.h>

#define NN 2000
#define BB 8
#define LL 12
#define DD 2
#define HH 64
#define EE 16000
#define ETOT 18000
#define NSEQ (NN*BB)                 // 16000
#define OUT1_ELEMS (NSEQ*LL*HH)      // 12,288,000
#define NPB 14                       // nodes per precompute block
#define PRE_GRID ((NN + NPB - 1) / NPB)

__device__ float g_out1[OUT1_ELEMS];
__device__ float g_agg[OUT1_ELEMS];
__device__ float g_Y[(size_t)NN * 6 * 96 * 64];   // 294.9 MB: per-node planes

// ---------------------------------------------------------------------------
// FMA-only fast math (no MUFU)
// ---------------------------------------------------------------------------
__device__ __forceinline__ float fexp2(float y) {
    y = fminf(fmaxf(y, -125.0f), 125.0f);
    float r = __fadd_rn(y, 12582912.0f);
    int   n = __float_as_int(r) - 0x4B400000;
    float f = __fsub_rn(y, __fsub_rn(r, 12582912.0f));
    float u = f * 0.69314718055994531f;
    float p = fmaf(u, 1.3888889e-3f, 8.3333333e-3f);
    p = fmaf(u, p, 4.1666667e-2f);
    p = fmaf(u, p, 1.6666667e-1f);
    p = fmaf(u, p, 0.5f);
    p = fmaf(u, p, 1.0f);
    p = fmaf(u, p, 1.0f);
    return p * __int_as_float((n + 127) << 23);
}
__device__ __forceinline__ float frcp(float x) {
    float r = __int_as_float(0x7EF311C3 - __float_as_int(x));
    r = r * __fmaf_rn(-x, r, 2.0f);
    r = r * __fmaf_rn(-x, r, 2.0f);
    r = r * __fmaf_rn(-x, r, 2.0f);
    return r;
}
__device__ __forceinline__ float fsig(float x) {
    return frcp(1.0f + fexp2(-1.4426950408889634f * x));
}
__device__ __forceinline__ float ftanh(float x) {
    float e = fexp2(2.8853900817779268f * x);
    return fmaf(-2.0f, frcp(1.0f + e), 1.0f);
}

// ---------------------------------------------------------------------------
// mma.sync / ldmatrix helpers (sm_80+ path, legal on sm_103)
// ---------------------------------------------------------------------------
__device__ __forceinline__ uint32_t smem_u32(const void* p) {
    uint32_t a;
    asm("{ .reg .u64 t; cvta.to.shared.u64 t, %1; cvt.u32.u64 %0, t; }"
        : "=r"(a) : "l"(p));
    return a;
}
__device__ __forceinline__ void ldmx4(uint32_t* r, uint32_t addr) {
    asm volatile("ldmatrix.sync.aligned.m8n8.x4.shared.b16 {%0,%1,%2,%3}, [%4];"
                 : "=r"(r[0]), "=r"(r[1]), "=r"(r[2]), "=r"(r[3]) : "r"(addr));
}
__device__ __forceinline__ void mma16816(float* d, const uint32_t* a, const uint32_t* b) {
    asm volatile("mma.sync.aligned.m16n8k16.row.col.f32.bf16.bf16.f32 "
                 "{%0,%1,%2,%3}, {%4,%5,%6,%7}, {%8,%9}, {%0,%1,%2,%3};"
                 : "+f"(d[0]), "+f"(d[1]), "+f"(d[2]), "+f"(d[3])
                 : "r"(a[0]), "r"(a[1]), "r"(a[2]), "r"(a[3]),
                   "r"(b[0]), "r"(b[1]));
}
// tiles with 64 bf16 per row (128 B = 8 x 16B units), unit ^= (row&7)
__device__ __forceinline__ uint32_t tb64(int row, int k) {
    return (uint32_t)(row * 8 + ((k >> 3) ^ (row & 7))) * 16u
         + (uint32_t)(k & 7) * 2u;
}

// ---------------------------------------------------------------------------
// GRU1 (unchanged, proven)
// ---------------------------------------------------------------------------
extern "C" __global__ void gru1_kernel(const float* __restrict__ data,
                                       const float* __restrict__ Wih,
                                       const float* __restrict__ Whh,
                                       const float* __restrict__ bih,
                                       const float* __restrict__ bhh,
                                       float* __restrict__ h1_out)
{
    extern __shared__ float sm[];
    float* whhT = sm;
    float* h_sh = sm + 12352;
    float* x_sh = sm + 12352 + 1024;

    const int tid = threadIdx.x;
    const int grp = tid >> 6;
    const int j   = tid & 63;

    for (int idx = tid; idx < 12288; idx += 256) {
        int g = idx >> 6, k = idx & 63;
        int m = g >> 6, jj = g & 63;
        whhT[k * 193 + m * 64 + jj] = Whh[idx];
    }
    for (int idx = tid; idx < 384; idx += 256)
        x_sh[idx] = data[(size_t)blockIdx.x * 384 + idx];

    float wr0 = Wih[j * 2],        wr1 = Wih[j * 2 + 1];
    float wz0 = Wih[(64 + j) * 2], wz1 = Wih[(64 + j) * 2 + 1];
    float wn0 = Wih[(128 + j)* 2], wn1 = Wih[(128 + j)* 2 + 1];
    float br = bih[j], bz = bih[64 + j], bn = bih[128 + j];
    float cr = bhh[j], cz = bhh[64 + j], cn = bhh[128 + j];

    float h[4] = {0.f, 0.f, 0.f, 0.f};
    const int s0 = blockIdx.x * 16 + grp * 4;
    float* outb = g_out1 + (size_t)s0 * 768 + j;

    for (int l = 0; l < LL; l++) {
        *(float4*)&h_sh[grp * 256 + j * 4] = make_float4(h[0], h[1], h[2], h[3]);
        __syncthreads();

        float ghr[4], ghz[4], ghn[4];
        #pragma unroll
        for (int s = 0; s < 4; s++) { ghr[s] = cr; ghz[s] = cz; ghn[s] = cn; }

        const float* wp = whhT + j;
        const float* hp = h_sh + grp * 256;
        #pragma unroll 4
        for (int k = 0; k < 64; k++) {
            float w0 = wp[k * 193];
            float w1 = wp[k * 193 + 64];
            float w2 = wp[k * 193 + 128];
            float4 hv = *(const float4*)&hp[k * 4];
            ghr[0] = fmaf(hv.x, w0, ghr[0]); ghz[0] = fmaf(hv.x, w1, ghz[0]); ghn[0] = fmaf(hv.x, w2, ghn[0]);
            ghr[1] = fmaf(hv.y, w0, ghr[1]); ghz[1] = fmaf(hv.y, w1, ghz[1]); ghn[1] = fmaf(hv.y, w2, ghn[1]);
            ghr[2] = fmaf(hv.z, w0, ghr[2]); ghz[2] = fmaf(hv.z, w1, ghz[2]); ghn[2] = fmaf(hv.z, w2, ghn[2]);
            ghr[3] = fmaf(hv.w, w0, ghr[3]); ghz[3] = fmaf(hv.w, w1, ghz[3]); ghn[3] = fmaf(hv.w, w2, ghn[3]);
        }
        #pragma unroll
        for (int s = 0; s < 4; s++) {
            float x0 = x_sh[(grp * 4 + s) * 24 + l * 2];
            float x1 = x_sh[(grp * 4 + s) * 24 + l * 2 + 1];
            float gir = fmaf(x1, wr1, fmaf(x0, wr0, br));
            float giz = fmaf(x1, wz1, fmaf(x0, wz0, bz));
            float gin = fmaf(x1, wn1, fmaf(x0, wn0, bn));
            float r = fsig(gir + ghr[s]);
            float z = fsig(giz + ghz[s]);
            float n = ftanh(fmaf(r, ghn[s], gin));
            h[s] = fmaf(z, h[s] - n, n);
            outb[s * 768 + l * 64] = h[s];
        }
        __syncthreads();
    }
    #pragma unroll
    for (int s = 0; s < 4; s++)
        h1_out[(s0 + s) * 64 + j] = h[s];
}

// ---------------------------------------------------------------------------
extern "C" __global__ void zero_agg_kernel()
{
    for (int i = blockIdx.x * blockDim.x + threadIdx.x; i < OUT1_ELEMS;
         i += gridDim.x * blockDim.x)
        g_agg[i] = 0.0f;
}

// ---------------------------------------------------------------------------
// Precompute kernel: per node n, Y[n][t] = X[n] @ Bmat_t  (t = 6 planes),
// M=96, K=64, N=384 via mma.sync bf16 hi/lo split (3 products).
// Bmat[n=t*64+h][k]:
//   t in {0,1}: W3[(k*64+h)*2 + t]        (top, h0/h1 coeff)
//   t == 2   : b3[k*64+h]                 (top, const)
//   t in {3,4}: W3[((64+k)*64+h)*2 + t-3] (bottom)
//   t == 5   : b3[(64+k)*64+h]
// smem: BH 48K @0, BL 48K @49152, XH 12K @98304, XL 12K @110592  (120 KB)
// ---------------------------------------------------------------------------
#define PC_BH 0
#define PC_BL 49152
#define PC_XH 98304
#define PC_XL 110592
#define PC_SMEM 122880

extern "C" __global__ void __launch_bounds__(256, 1)
precomp_kernel(const float* __restrict__ W3, const float* __restrict__ b3)
{
    extern __shared__ char smc[];
    const uint32_t sb = smem_u32(smc);
    const int tid = threadIdx.x, wid = tid >> 5, lid = tid & 31;

    // ---- stage Bmat hi/lo (one-time per CTA) ----
    for (int i = tid; i < 12288; i += 256) {      // (n, k/2)
        int n = i >> 5, k = (i & 31) * 2;
        int t = n >> 6, h = n & 63;
        int base = (t >= 3) ? 64 : 0;
        int c = t - (t >= 3 ? 3 : 0);
        int m0 = (base + k) * 64 + h;
        int m1 = m0 + 64;
        float v0 = (c == 2) ? b3[m0] : W3[m0 * 2 + c];
        float v1 = (c == 2) ? b3[m1] : W3[m1 * 2 + c];
        __nv_bfloat16 hx = __float2bfloat16(v0);
        __nv_bfloat16 hy = __float2bfloat16(v1);
        __nv_bfloat16 lx = __float2bfloat16(v0 - __bfloat162float(hx));
        __nv_bfloat16 ly = __float2bfloat16(v1 - __bfloat162float(hy));
        uint32_t off = tb64(n, k);
        __nv_bfloat162 th; th.x = hx; th.y = hy;
        __nv_bfloat162 tl; tl.x = lx; tl.y = ly;
        *(__nv_bfloat162*)(smc + PC_BH + off) = th;
        *(__nv_bfloat162*)(smc + PC_BL + off) = tl;
    }
    __syncthreads();

    // fragment lane constants (proven in R7)
    const int ar  = (lid & 7) + ((lid >> 3) & 1) * 8;
    const int aku = lid >> 4;
    const int br  = (lid & 7) + ((lid >> 4) << 3);
    const int bku = (lid >> 3) & 1;

    const int n0 = blockIdx.x * NPB;
    for (int ni = 0; ni < NPB; ni++) {
        const int node = n0 + ni;
        if (node >= NN) break;

        // ---- stage X[node] hi/lo (96x64) ----
        {
            const float* xp = g_out1 + (size_t)node * 6144;
            for (int i = tid; i < 3072; i += 256) {
                int r = i >> 5, k = (i & 31) * 2;
                float2 v = *(const float2*)(xp + r * 64 + k);
                __nv_bfloat16 hx = __float2bfloat16(v.x);
                __nv_bfloat16 hy = __float2bfloat16(v.y);
                __nv_bfloat16 lx = __float2bfloat16(v.x - __bfloat162float(hx));
                __nv_bfloat16 ly = __float2bfloat16(v.y - __bfloat162float(hy));
                uint32_t off = tb64(r, k);
                __nv_bfloat162 th; th.x = hx; th.y = hy;
                __nv_bfloat162 tl; tl.x = lx; tl.y = ly;
                *(__nv_bfloat162*)(smc + PC_XH + off) = th;
                *(__nv_bfloat162*)(smc + PC_XL + off) = tl;
            }
        }
        __syncthreads();

        if (wid < 6) {
            const int mw = wid >> 1, nw = wid & 1;   // 3 m32 x 2 n32
            const int arow0 = mw * 32 + ar;
            const int arow1 = arow0 + 16;
            const uint32_t ab0 = (uint32_t)arow0 * 128u, ax0 = (uint32_t)(arow0 & 7);
            const uint32_t ab1 = (uint32_t)arow1 * 128u, ax1 = (uint32_t)(arow1 & 7);

            #pragma unroll
            for (int t = 0; t < 6; t++) {
                float acc[2][4][4];
                #pragma unroll
                for (int a = 0; a < 2; a++)
                    #pragma unroll
                    for (int b = 0; b < 4; b++)
                        #pragma unroll
                        for (int c = 0; c < 4; c++) acc[a][b][c] = 0.0f;

                const int brow0 = t * 64 + nw * 32 + br;
                const int brow1 = brow0 + 16;
                const uint32_t bb0 = (uint32_t)brow0 * 128u, bx0 = (uint32_t)(brow0 & 7);
                const uint32_t bb1 = (uint32_t)brow1 * 128u, bx1 = (uint32_t)(brow1 & 7);

                #pragma unroll
                for (int sp = 0; sp < 3; sp++) {
                    const uint32_t Ab = sb + (sp == 2 ? PC_XL : PC_XH);
                    const uint32_t Bb = sb + (sp == 1 ? PC_BL : PC_BH);
                    #pragma unroll
                    for (int ks = 0; ks < 4; ks++) {
                        const uint32_t kb = (uint32_t)(ks * 2);
                        uint32_t af0[4], af1[4], bf0[4], bf1[4];
                        ldmx4(af0, Ab + ab0 + (((kb + aku) ^ ax0) << 4));
                        ldmx4(af1, Ab + ab1 + (((kb + aku) ^ ax1) << 4));
                        ldmx4(bf0, Bb + bb0 + (((kb + bku) ^ bx0) << 4));
                        ldmx4(bf1, Bb + bb1 + (((kb + bku) ^ bx1) << 4));
                        mma16816(acc[0][0], af0, bf0);
                        mma16816(acc[0][1], af0, bf0 + 2);
                        mma16816(acc[0][2], af0, bf1);
                        mma16816(acc[0][3], af0, bf1 + 2);
                        mma16816(acc[1][0], af1, bf0);
                        mma16816(acc[1][1], af1, bf0 + 2);
                        mma16816(acc[1][2], af1, bf1);
                        mma16816(acc[1][3], af1, bf1 + 2);
                    }
                }
                // write plane t
                float* yp = g_Y + ((size_t)node * 6 + t) * 6144;
                const int g = lid >> 2, c2 = (lid & 3) * 2;
                #pragma unroll
                for (int mt = 0; mt < 2; mt++) {
                    const int r0 = mw * 32 + mt * 16 + g;
                    const int r1 = r0 + 8;
                    #pragma unroll
                    for (int nt = 0; nt < 4; nt++) {
                        const int c0 = nw * 32 + nt * 8 + c2;
                        float2 p0; p0.x = acc[mt][nt][0]; p0.y = acc[mt][nt][1];
                        float2 p1; p1.x = acc[mt][nt][2]; p1.y = acc[mt][nt][3];
                        *(float2*)(yp + r0 * 64 + c0) = p0;
                        *(float2*)(yp + r1 * 64 + c0) = p1;
                    }
                }
            }
        }
        __syncthreads();   // before next node's X overwrite
    }
}

// ---------------------------------------------------------------------------
// Edge streaming kernel: alpha = h0*(A0[i]+B0[j]) + h1*(A1[i]+B1[j]) + (A2[i]+B2[j])
// then leaky_relu -> batch-softmax -> msg (uses g_out1[src]) -> red.global.add.v4
// smem: feats @64, hdn @576, hdn2 @640, alpha 24KB @1024.  (25.6 KB)
// ---------------------------------------------------------------------------
#define ES_SMEM (1024 + 24576)

extern "C" __global__ void __launch_bounds__(256)
edge_stream_kernel(const float* __restrict__ features,
                   const int* __restrict__ ei,
                   const float* __restrict__ W1,
                   const float* __restrict__ b1,
                   const float* __restrict__ W2,
                   const float* __restrict__ b2)
{
    extern __shared__ char smc[];
    float* feats = (float*)(smc + 64);
    float* hdn   = (float*)(smc + 576);
    float* hdn2  = (float*)(smc + 640);
    float* al    = (float*)(smc + 1024);

    const int tid = threadIdx.x;
    const int e = blockIdx.x;
    int src, dst;
    if (e < EE) { src = ei[e]; dst = ei[EE + e]; }
    else        { src = dst = e - EE; }

    if (tid < 128)
        feats[tid] = (tid < 64) ? features[dst * 64 + tid]
                                : features[src * 64 + (tid - 64)];
    __syncthreads();

    if (tid < 16) {
        float acc = b1[tid];
        const float* wrow = W1 + tid * 128;
        #pragma unroll 8
        for (int k = 0; k < 128; k++) acc = fmaf(feats[k], wrow[k], acc);
        hdn[tid] = fsig(acc);
    }
    __syncthreads();
    if (tid < 2) {
        float acc = b2[tid];
        const float* wrow = W2 + tid * 16;
        #pragma unroll
        for (int k = 0; k < 16; k++) acc = fmaf(hdn[k], wrow[k], acc);
        hdn2[tid] = fsig(acc);
    }
    __syncthreads();

    const float h0 = hdn2[0], h1 = hdn2[1];
    const float4* Ad = (const float4*)(g_Y + (size_t)dst * 36864);          // planes 0..2
    const float4* Bs = (const float4*)(g_Y + (size_t)src * 36864 + 18432);  // planes 3..5

    #pragma unroll 2
    for (int i = tid; i < 1536; i += 256) {
        float4 a0 = Ad[i], a1 = Ad[1536 + i], a2 = Ad[3072 + i];
        float4 b0 = Bs[i], b1v = Bs[1536 + i], b2v = Bs[3072 + i];
        float4 v;
        v.x = fmaf(h0, a0.x + b0.x, fmaf(h1, a1.x + b1v.x, a2.x + b2v.x));
        v.y = fmaf(h0, a0.y + b0.y, fmaf(h1, a1.y + b1v.y, a2.y + b2v.y));
        v.z = fmaf(h0, a0.z + b0.z, fmaf(h1, a1.z + b1v.z, a2.z + b2v.z));
        v.w = fmaf(h0, a0.w + b0.w, fmaf(h1, a1.w + b1v.w, a2.w + b2v.w));
        v.x = v.x > 0.f ? v.x : 0.01f * v.x;
        v.y = v.y > 0.f ? v.y : 0.01f * v.y;
        v.z = v.z > 0.f ? v.z : 0.01f * v.z;
        v.w = v.w > 0.f ? v.w : 0.01f * v.w;
        int m = i >> 4, c4 = i & 15;
        *(float4*)&al[m * 64 + 4 * (c4 ^ (m & 15))] = v;
    }
    __syncthreads();

    // ---- softmax over batch (8) + msg + vector atomic scatter (proven) ----
    if (tid < 192) {
        const int l = tid >> 4, h4 = tid & 15;
        float4 a[8];
        float4 mx = make_float4(-1e30f, -1e30f, -1e30f, -1e30f);
        #pragma unroll
        for (int b = 0; b < 8; b++) {
            int m = b * 12 + l;
            a[b] = *(const float4*)&al[m * 64 + 4 * (h4 ^ (m & 15))];
            mx.x = fmaxf(mx.x, a[b].x); mx.y = fmaxf(mx.y, a[b].y);
            mx.z = fmaxf(mx.z, a[b].z); mx.w = fmaxf(mx.w, a[b].w);
        }
        float4 ssum = make_float4(0.f, 0.f, 0.f, 0.f);
        #pragma unroll
        for (int b = 0; b < 8; b++) {
            a[b].x = fexp2(1.4426950408889634f * (a[b].x - mx.x));
            a[b].y = fexp2(1.4426950408889634f * (a[b].y - mx.y));
            a[b].z = fexp2(1.4426950408889634f * (a[b].z - mx.z));
            a[b].w = fexp2(1.4426950408889634f * (a[b].w - mx.w));
            ssum.x += a[b].x; ssum.y += a[b].y; ssum.z += a[b].z; ssum.w += a[b].w;
        }
        float4 inv = make_float4(frcp(ssum.x), frcp(ssum.y), frcp(ssum.z), frcp(ssum.w));
        float* aggb = g_agg + (size_t)dst * 6144;
        const float4* xj = (const float4*)(g_out1 + (size_t)src * 6144);
        #pragma unroll
        for (int b = 0; b < 8; b++) {
            int m = b * 12 + l;
            float4 sj = xj[m * 16 + h4];
            float4 msg;
            msg.x = a[b].x * inv.x * sj.x;
            msg.y = a[b].y * inv.y * sj.y;
            msg.z = a[b].z * inv.z * sj.z;
            msg.w = a[b].w * inv.w * sj.w;
            asm volatile("red.global.add.v4.f32 [%0], {%1,%2,%3,%4};"
                         :: "l"(aggb + m * 64 + h4 * 4), "f"(msg.x), "f"(msg.y),
                            "f"(msg.z), "f"(msg.w) : "memory");
        }
    }
}

// ---------------------------------------------------------------------------
// GRU2 (unchanged, proven)
// ---------------------------------------------------------------------------
extern "C" __global__ void gru2_kernel(const float* __restrict__ Wih,
                                       const float* __restrict__ Whh,
                                       const float* __restrict__ bih,
                                       const float* __restrict__ bhh,
                                       float* __restrict__ h2_out)
{
    extern __shared__ float sm[];
    float* wT   = sm;
    float* h_sh = sm + 24640;
    float* x_sh = sm + 24640 + 1024;

    const int tid = threadIdx.x;
    const int grp = tid >> 6;
    const int j   = tid & 63;

    for (int idx = tid; idx < 12288; idx += 256) {
        int g = idx >> 6, k = idx & 63;
        int m = g >> 6, jj = g & 63;
        wT[k * 385 + m * 64 + jj]       = Wih[idx];
        wT[k * 385 + 192 + m * 64 + jj] = Whh[idx];
    }

    float br = bih[j], bz = bih[64 + j], bn = bih[128 + j];
    float cr = bhh[j], cz = bhh[64 + j], cn = bhh[128 + j];

    float h[4] = {0.f, 0.f, 0.f, 0.f};
    const int s0 = blockIdx.x * 16 + grp * 4;
    const float* xg = g_agg + (size_t)s0 * 768 + j;

    for (int l = 0; l < LL; l++) {
        float4 xv;
        xv.x = fmaxf(xg[0 * 768 + l * 64], 0.0f);
        xv.y = fmaxf(xg[1 * 768 + l * 64], 0.0f);
        xv.z = fmaxf(xg[2 * 768 + l * 64], 0.0f);
        xv.w = fmaxf(xg[3 * 768 + l * 64], 0.0f);
        *(float4*)&x_sh[grp * 256 + j * 4] = xv;
        *(float4*)&h_sh[grp * 256 + j * 4] = make_float4(h[0], h[1], h[2], h[3]);
        __syncthreads();

        float gr[4], gz[4], gn[4];
        #pragma unroll
        for (int s = 0; s < 4; s++) { gr[s] = br + cr; gz[s] = bz + cz; gn[s] = bn; }
        float ghn[4] = {cn, cn, cn, cn};

        const float* wp = wT + j;
        const float* hp = h_sh + grp * 256;
        const float* xp = x_sh + grp * 256;
        #pragma unroll 2
        for (int k = 0; k < 64; k++) {
            float wi0 = wp[k * 385];
            float wi1 = wp[k * 385 + 64];
            float wi2 = wp[k * 385 + 128];
            float wh0 = wp[k * 385 + 192];
            float wh1 = wp[k * 385 + 256];
            float wh2 = wp[k * 385 + 320];
            float4 xk = *(const float4*)&xp[k * 4];
            float4 hk = *(const float4*)&hp[k * 4];
            gr[0] = fmaf(xk.x, wi0, gr[0]); gz[0] = fmaf(xk.x, wi1, gz[0]); gn[0] = fmaf(xk.x, wi2, gn[0]);
            gr[0] = fmaf(hk.x, wh0, gr[0]); gz[0] = fmaf(hk.x, wh1, gz[0]); ghn[0] = fmaf(hk.x, wh2, ghn[0]);
            gr[1] = fmaf(xk.y, wi0, gr[1]); gz[1] = fmaf(xk.y, wi1, gz[1]); gn[1] = fmaf(xk.y, wi2, gn[1]);
            gr[1] = fmaf(hk.y, wh0, gr[1]); gz[1] = fmaf(hk.y, wh1, gz[1]); ghn[1] = fmaf(hk.y, wh2, ghn[1]);
            gr[2] = fmaf(xk.z, wi0, gr[2]); gz[2] = fmaf(xk.z, wi1, gz[2]); gn[2] = fmaf(xk.z, wi2, gn[2]);
            gr[2] = fmaf(hk.z, wh0, gr[2]); gz[2] = fmaf(hk.z, wh1, gz[2]); ghn[2] = fmaf(hk.z, wh2, ghn[2]);
            gr[3] = fmaf(xk.w, wi0, gr[3]); gz[3] = fmaf(xk.w, wi1, gz[3]); gn[3] = fmaf(xk.w, wi2, gn[3]);
            gr[3] = fmaf(hk.w, wh0, gr[3]); gz[3] = fmaf(hk.w, wh1, gz[3]); ghn[3] = fmaf(hk.w, wh2, ghn[3]);
        }
        #pragma unroll
        for (int s = 0; s < 4; s++) {
            float r = fsig(gr[s]);
            float z = fsig(gz[s]);
            float n = ftanh(fmaf(r, ghn[s], gn[s]));
            h[s] = fmaf(z, h[s] - n, n);
        }
        __syncthreads();
    }
    #pragma unroll
    for (int s = 0; s < 4; s++)
        h2_out[(s0 + s) * 64 + j] = h[s];
}

// ---------------------------------------------------------------------------

static const int GRU1_SMEM = (12352 + 1024 + 384) * 4;
static const int GRU2_SMEM = (24640 + 1024 + 1024) * 4;

extern "C" void kernel_launch(void* const* d_in, const int* in_sizes, int n_in,
                              void* d_out, int out_size)
{
    const float* data     = (const float*)d_in[0];
    const float* features = (const float*)d_in[1];
    const int*   ei       = (const int*)  d_in[2];
    const float* Wih1     = (const float*)d_in[3];
    const float* Whh1     = (const float*)d_in[4];
    const float* bih1     = (const float*)d_in[5];
    const float* bhh1     = (const float*)d_in[6];
    const float* W1       = (const float*)d_in[7];
    const float* b1       = (const float*)d_in[8];
    const float* W2       = (const float*)d_in[9];
    const float* b2       = (const float*)d_in[10];
    const float* W3       = (const float*)d_in[11];
    const float* b3       = (const float*)d_in[12];
    const float* Wih2     = (const float*)d_in[13];
    const float* Whh2     = (const float*)d_in[14];
    const float* bih2     = (const float*)d_in[15];
    const float* bhh2     = (const float*)d_in[16];
    float* out = (float*)d_out;

    cudaFuncSetAttribute(gru1_kernel, cudaFuncAttributeMaxDynamicSharedMemorySize, GRU1_SMEM);
    cudaFuncSetAttribute(gru2_kernel, cudaFuncAttributeMaxDynamicSharedMemorySize, GRU2_SMEM);
    cudaFuncSetAttribute(precomp_kernel, cudaFuncAttributeMaxDynamicSharedMemorySize, PC_SMEM);

    gru1_kernel<<<NSEQ / 16, 256, GRU1_SMEM>>>(data, Wih1, Whh1, bih1, bhh1, out);
    precomp_kernel<<<PRE_GRID, 256, PC_SMEM>>>(W3, b3);
    zero_agg_kernel<<<2048, 256>>>();
    edge_stream_kernel<<<ETOT, 256, ES_SMEM>>>(features, ei, W1, b1, W2, b2);
    gru2_kernel<<<NSEQ / 16, 256, GRU2_SMEM>>>(Wih2, Whh2, bih2, bhh2, out + NSEQ * HH);
}

// round 13
// speedup vs baseline: 2.2502x; 1.1706x over previous
#include <cuda_runtime.h>
#include <cuda_bf16.h>
#include <cuda_fp16.h>
#include <cstdint>
#include <stdint.h>
#include <math.h>

#define NN 2000
#define BB 8
#define LL 12
#define DD 2
#define HH 64
#define EE 16000
#define ETOT 18000
#define NSEQ (NN*BB)                 // 16000
#define OUT1_ELEMS (NSEQ*LL*HH)      // 12,288,000
#define NPB 14                       // nodes per precompute block
#define PRE_GRID ((NN + NPB - 1) / NPB)

__device__ float  g_out1[OUT1_ELEMS];
__device__ float  g_agg[OUT1_ELEMS];
__device__ __half g_Yh[(size_t)NN * 6 * 96 * 64];   // 147.5 MB fp16 planes

// ---------------------------------------------------------------------------
// FMA-only fast math (no MUFU)
// ---------------------------------------------------------------------------
__device__ __forceinline__ float fexp2(float y) {
    y = fminf(fmaxf(y, -125.0f), 125.0f);
    float r = __fadd_rn(y, 12582912.0f);
    int   n = __float_as_int(r) - 0x4B400000;
    float f = __fsub_rn(y, __fsub_rn(r, 12582912.0f));
    float u = f * 0.69314718055994531f;
    float p = fmaf(u, 1.3888889e-3f, 8.3333333e-3f);
    p = fmaf(u, p, 4.1666667e-2f);
    p = fmaf(u, p, 1.6666667e-1f);
    p = fmaf(u, p, 0.5f);
    p = fmaf(u, p, 1.0f);
    p = fmaf(u, p, 1.0f);
    return p * __int_as_float((n + 127) << 23);
}
__device__ __forceinline__ float frcp(float x) {
    float r = __int_as_float(0x7EF311C3 - __float_as_int(x));
    r = r * __fmaf_rn(-x, r, 2.0f);
    r = r * __fmaf_rn(-x, r, 2.0f);
    r = r * __fmaf_rn(-x, r, 2.0f);
    return r;
}
__device__ __forceinline__ float fsig(float x) {
    return frcp(1.0f + fexp2(-1.4426950408889634f * x));
}
__device__ __forceinline__ float ftanh(float x) {
    float e = fexp2(2.8853900817779268f * x);
    return fmaf(-2.0f, frcp(1.0f + e), 1.0f);
}

// ---------------------------------------------------------------------------
// mma.sync / ldmatrix helpers (sm_80+ path, legal on sm_103)
// ---------------------------------------------------------------------------
__device__ __forceinline__ uint32_t smem_u32(const void* p) {
    uint32_t a;
    asm("{ .reg .u64 t; cvta.to.shared.u64 t, %1; cvt.u32.u64 %0, t; }"
        : "=r"(a) : "l"(p));
    return a;
}
__device__ __forceinline__ void ldmx4(uint32_t* r, uint32_t addr) {
    asm volatile("ldmatrix.sync.aligned.m8n8.x4.shared.b16 {%0,%1,%2,%3}, [%4];"
                 : "=r"(r[0]), "=r"(r[1]), "=r"(r[2]), "=r"(r[3]) : "r"(addr));
}
__device__ __forceinline__ void mma16816(float* d, const uint32_t* a, const uint32_t* b) {
    asm volatile("mma.sync.aligned.m16n8k16.row.col.f32.bf16.bf16.f32 "
                 "{%0,%1,%2,%3}, {%4,%5,%6,%7}, {%8,%9}, {%0,%1,%2,%3};"
                 : "+f"(d[0]), "+f"(d[1]), "+f"(d[2]), "+f"(d[3])
                 : "r"(a[0]), "r"(a[1]), "r"(a[2]), "r"(a[3]),
                   "r"(b[0]), "r"(b[1]));
}
// tiles with 64 bf16 per row (128 B = 8 x 16B units), unit ^= (row&7)
__device__ __forceinline__ uint32_t tb64(int row, int k) {
    return (uint32_t)(row * 8 + ((k >> 3) ^ (row & 7))) * 16u
         + (uint32_t)(k & 7) * 2u;
}

// ---------------------------------------------------------------------------
// GRU1 (unchanged, proven)
// ---------------------------------------------------------------------------
extern "C" __global__ void gru1_kernel(const float* __restrict__ data,
                                       const float* __restrict__ Wih,
                                       const float* __restrict__ Whh,
                                       const float* __restrict__ bih,
                                       const float* __restrict__ bhh,
                                       float* __restrict__ h1_out)
{
    extern __shared__ float sm[];
    float* whhT = sm;
    float* h_sh = sm + 12352;
    float* x_sh = sm + 12352 + 1024;

    const int tid = threadIdx.x;
    const int grp = tid >> 6;
    const int j   = tid & 63;

    for (int idx = tid; idx < 12288; idx += 256) {
        int g = idx >> 6, k = idx & 63;
        int m = g >> 6, jj = g & 63;
        whhT[k * 193 + m * 64 + jj] = Whh[idx];
    }
    for (int idx = tid; idx < 384; idx += 256)
        x_sh[idx] = data[(size_t)blockIdx.x * 384 + idx];

    float wr0 = Wih[j * 2],        wr1 = Wih[j * 2 + 1];
    float wz0 = Wih[(64 + j) * 2], wz1 = Wih[(64 + j) * 2 + 1];
    float wn0 = Wih[(128 + j)* 2], wn1 = Wih[(128 + j)* 2 + 1];
    float br = bih[j], bz = bih[64 + j], bn = bih[128 + j];
    float cr = bhh[j], cz = bhh[64 + j], cn = bhh[128 + j];

    float h[4] = {0.f, 0.f, 0.f, 0.f};
    const int s0 = blockIdx.x * 16 + grp * 4;
    float* outb = g_out1 + (size_t)s0 * 768 + j;

    for (int l = 0; l < LL; l++) {
        *(float4*)&h_sh[grp * 256 + j * 4] = make_float4(h[0], h[1], h[2], h[3]);
        __syncthreads();

        float ghr[4], ghz[4], ghn[4];
        #pragma unroll
        for (int s = 0; s < 4; s++) { ghr[s] = cr; ghz[s] = cz; ghn[s] = cn; }

        const float* wp = whhT + j;
        const float* hp = h_sh + grp * 256;
        #pragma unroll 4
        for (int k = 0; k < 64; k++) {
            float w0 = wp[k * 193];
            float w1 = wp[k * 193 + 64];
            float w2 = wp[k * 193 + 128];
            float4 hv = *(const float4*)&hp[k * 4];
            ghr[0] = fmaf(hv.x, w0, ghr[0]); ghz[0] = fmaf(hv.x, w1, ghz[0]); ghn[0] = fmaf(hv.x, w2, ghn[0]);
            ghr[1] = fmaf(hv.y, w0, ghr[1]); ghz[1] = fmaf(hv.y, w1, ghz[1]); ghn[1] = fmaf(hv.y, w2, ghn[1]);
            ghr[2] = fmaf(hv.z, w0, ghr[2]); ghz[2] = fmaf(hv.z, w1, ghz[2]); ghn[2] = fmaf(hv.z, w2, ghn[2]);
            ghr[3] = fmaf(hv.w, w0, ghr[3]); ghz[3] = fmaf(hv.w, w1, ghz[3]); ghn[3] = fmaf(hv.w, w2, ghn[3]);
        }
        #pragma unroll
        for (int s = 0; s < 4; s++) {
            float x0 = x_sh[(grp * 4 + s) * 24 + l * 2];
            float x1 = x_sh[(grp * 4 + s) * 24 + l * 2 + 1];
            float gir = fmaf(x1, wr1, fmaf(x0, wr0, br));
            float giz = fmaf(x1, wz1, fmaf(x0, wz0, bz));
            float gin = fmaf(x1, wn1, fmaf(x0, wn0, bn));
            float r = fsig(gir + ghr[s]);
            float z = fsig(giz + ghz[s]);
            float n = ftanh(fmaf(r, ghn[s], gin));
            h[s] = fmaf(z, h[s] - n, n);
            outb[s * 768 + l * 64] = h[s];
        }
        __syncthreads();
    }
    #pragma unroll
    for (int s = 0; s < 4; s++)
        h1_out[(s0 + s) * 64 + j] = h[s];
}

// ---------------------------------------------------------------------------
extern "C" __global__ void zero_agg_kernel()
{
    float4 z = make_float4(0.f, 0.f, 0.f, 0.f);
    for (int i = blockIdx.x * blockDim.x + threadIdx.x; i < OUT1_ELEMS / 4;
         i += gridDim.x * blockDim.x)
        ((float4*)g_agg)[i] = z;
}

// ---------------------------------------------------------------------------
// Precompute kernel: per node n, Y[n][t] = X[n] @ Bmat_t  (6 planes, fp16 out)
// M=96, K=64, N=384 via mma.sync bf16 hi/lo split (3 products).
// smem: BH 48K @0, BL 48K @49152, XH 12K @98304, XL 12K @110592  (120 KB)
// ---------------------------------------------------------------------------
#define PC_BH 0
#define PC_BL 49152
#define PC_XH 98304
#define PC_XL 110592
#define PC_SMEM 122880

extern "C" __global__ void __launch_bounds__(256, 1)
precomp_kernel(const float* __restrict__ W3, const float* __restrict__ b3)
{
    extern __shared__ char smc[];
    const uint32_t sb = smem_u32(smc);
    const int tid = threadIdx.x, wid = tid >> 5, lid = tid & 31;

    // ---- stage Bmat hi/lo (one-time per CTA) ----
    for (int i = tid; i < 12288; i += 256) {      // (n, k/2)
        int n = i >> 5, k = (i & 31) * 2;
        int t = n >> 6, h = n & 63;
        int base = (t >= 3) ? 64 : 0;
        int c = t - (t >= 3 ? 3 : 0);
        int m0 = (base + k) * 64 + h;
        int m1 = m0 + 64;
        float v0 = (c == 2) ? b3[m0] : W3[m0 * 2 + c];
        float v1 = (c == 2) ? b3[m1] : W3[m1 * 2 + c];
        __nv_bfloat16 hx = __float2bfloat16(v0);
        __nv_bfloat16 hy = __float2bfloat16(v1);
        __nv_bfloat16 lx = __float2bfloat16(v0 - __bfloat162float(hx));
        __nv_bfloat16 ly = __float2bfloat16(v1 - __bfloat162float(hy));
        uint32_t off = tb64(n, k);
        __nv_bfloat162 th; th.x = hx; th.y = hy;
        __nv_bfloat162 tl; tl.x = lx; tl.y = ly;
        *(__nv_bfloat162*)(smc + PC_BH + off) = th;
        *(__nv_bfloat162*)(smc + PC_BL + off) = tl;
    }
    __syncthreads();

    const int ar  = (lid & 7) + ((lid >> 3) & 1) * 8;
    const int aku = lid >> 4;
    const int br  = (lid & 7) + ((lid >> 4) << 3);
    const int bku = (lid >> 3) & 1;

    const int n0 = blockIdx.x * NPB;
    for (int ni = 0; ni < NPB; ni++) {
        const int node = n0 + ni;
        if (node >= NN) break;

        // ---- stage X[node] hi/lo (96x64) ----
        {
            const float* xp = g_out1 + (size_t)node * 6144;
            for (int i = tid; i < 3072; i += 256) {
                int r = i >> 5, k = (i & 31) * 2;
                float2 v = *(const float2*)(xp + r * 64 + k);
                __nv_bfloat16 hx = __float2bfloat16(v.x);
                __nv_bfloat16 hy = __float2bfloat16(v.y);
                __nv_bfloat16 lx = __float2bfloat16(v.x - __bfloat162float(hx));
                __nv_bfloat16 ly = __float2bfloat16(v.y - __bfloat162float(hy));
                uint32_t off = tb64(r, k);
                __nv_bfloat162 th; th.x = hx; th.y = hy;
                __nv_bfloat162 tl; tl.x = lx; tl.y = ly;
                *(__nv_bfloat162*)(smc + PC_XH + off) = th;
                *(__nv_bfloat162*)(smc + PC_XL + off) = tl;
            }
        }
        __syncthreads();

        if (wid < 6) {
            const int mw = wid >> 1, nw = wid & 1;   // 3 m32 x 2 n32
            const int arow0 = mw * 32 + ar;
            const int arow1 = arow0 + 16;
            const uint32_t ab0 = (uint32_t)arow0 * 128u, ax0 = (uint32_t)(arow0 & 7);
            const uint32_t ab1 = (uint32_t)arow1 * 128u, ax1 = (uint32_t)(arow1 & 7);

            #pragma unroll
            for (int t = 0; t < 6; t++) {
                float acc[2][4][4];
                #pragma unroll
                for (int a = 0; a < 2; a++)
                    #pragma unroll
                    for (int b = 0; b < 4; b++)
                        #pragma unroll
                        for (int c = 0; c < 4; c++) acc[a][b][c] = 0.0f;

                const int brow0 = t * 64 + nw * 32 + br;
                const int brow1 = brow0 + 16;
                const uint32_t bb0 = (uint32_t)brow0 * 128u, bx0 = (uint32_t)(brow0 & 7);
                const uint32_t bb1 = (uint32_t)brow1 * 128u, bx1 = (uint32_t)(brow1 & 7);

                #pragma unroll
                for (int sp = 0; sp < 3; sp++) {
                    const uint32_t Ab = sb + (sp == 2 ? PC_XL : PC_XH);
                    const uint32_t Bb = sb + (sp == 1 ? PC_BL : PC_BH);
                    #pragma unroll
                    for (int ks = 0; ks < 4; ks++) {
                        const uint32_t kb = (uint32_t)(ks * 2);
                        uint32_t af0[4], af1[4], bf0[4], bf1[4];
                        ldmx4(af0, Ab + ab0 + (((kb + aku) ^ ax0) << 4));
                        ldmx4(af1, Ab + ab1 + (((kb + aku) ^ ax1) << 4));
                        ldmx4(bf0, Bb + bb0 + (((kb + bku) ^ bx0) << 4));
                        ldmx4(bf1, Bb + bb1 + (((kb + bku) ^ bx1) << 4));
                        mma16816(acc[0][0], af0, bf0);
                        mma16816(acc[0][1], af0, bf0 + 2);
                        mma16816(acc[0][2], af0, bf1);
                        mma16816(acc[0][3], af0, bf1 + 2);
                        mma16816(acc[1][0], af1, bf0);
                        mma16816(acc[1][1], af1, bf0 + 2);
                        mma16816(acc[1][2], af1, bf1);
                        mma16816(acc[1][3], af1, bf1 + 2);
                    }
                }
                // write plane t (fp16)
                __half* yp = g_Yh + ((size_t)node * 6 + t) * 6144;
                const int g = lid >> 2, c2 = (lid & 3) * 2;
                #pragma unroll
                for (int mt = 0; mt < 2; mt++) {
                    const int r0 = mw * 32 + mt * 16 + g;
                    const int r1 = r0 + 8;
                    #pragma unroll
                    for (int nt = 0; nt < 4; nt++) {
                        const int c0 = nw * 32 + nt * 8 + c2;
                        *(__half2*)(yp + r0 * 64 + c0) =
                            __floats2half2_rn(acc[mt][nt][0], acc[mt][nt][1]);
                        *(__half2*)(yp + r1 * 64 + c0) =
                            __floats2half2_rn(acc[mt][nt][2], acc[mt][nt][3]);
                    }
                }
            }
        }
        __syncthreads();   // before next node's X overwrite
    }
}

// ---------------------------------------------------------------------------
// Edge streaming kernel (fp16 planes):
// alpha = h0*(A0[i]+B0[j]) + h1*(A1[i]+B1[j]) + (A2[i]+B2[j])
// leaky_relu -> batch-softmax -> msg (f32 stj) -> red.global.add.v4
// smem: feats @64, hdn @576, hdn2 @640, alpha 24KB @1024.  (25.6 KB)
// ---------------------------------------------------------------------------
#define ES_SMEM (1024 + 24576)

__device__ __forceinline__ float4 h4_to_f4(uint2 u) {
    float2 lo = __half22float2(*(__half2*)&u.x);
    float2 hi = __half22float2(*(__half2*)&u.y);
    float4 r; r.x = lo.x; r.y = lo.y; r.z = hi.x; r.w = hi.y;
    return r;
}

extern "C" __global__ void __launch_bounds__(256)
edge_stream_kernel(const float* __restrict__ features,
                   const int* __restrict__ ei,
                   const float* __restrict__ W1,
                   const float* __restrict__ b1,
                   const float* __restrict__ W2,
                   const float* __restrict__ b2)
{
    extern __shared__ char smc[];
    float* feats = (float*)(smc + 64);
    float* hdn   = (float*)(smc + 576);
    float* hdn2  = (float*)(smc + 640);
    float* al    = (float*)(smc + 1024);

    const int tid = threadIdx.x;
    const int e = blockIdx.x;
    int src, dst;
    if (e < EE) { src = ei[e]; dst = ei[EE + e]; }
    else        { src = dst = e - EE; }

    if (tid < 128)
        feats[tid] = (tid < 64) ? features[dst * 64 + tid]
                                : features[src * 64 + (tid - 64)];
    __syncthreads();

    if (tid < 16) {
        float acc = b1[tid];
        const float* wrow = W1 + tid * 128;
        #pragma unroll 8
        for (int k = 0; k < 128; k++) acc = fmaf(feats[k], wrow[k], acc);
        hdn[tid] = fsig(acc);
    }
    __syncthreads();
    if (tid < 2) {
        float acc = b2[tid];
        const float* wrow = W2 + tid * 16;
        #pragma unroll
        for (int k = 0; k < 16; k++) acc = fmaf(hdn[k], wrow[k], acc);
        hdn2[tid] = fsig(acc);
    }
    __syncthreads();

    const float h0 = hdn2[0], h1 = hdn2[1];
    const uint2* Ad = (const uint2*)(g_Yh + (size_t)dst * 36864);          // planes 0..2
    const uint2* Bs = (const uint2*)(g_Yh + (size_t)src * 36864 + 18432);  // planes 3..5

    #pragma unroll 2
    for (int i = tid; i < 1536; i += 256) {
        float4 a0 = h4_to_f4(Ad[i]);
        float4 a1 = h4_to_f4(Ad[1536 + i]);
        float4 a2 = h4_to_f4(Ad[3072 + i]);
        float4 b0 = h4_to_f4(Bs[i]);
        float4 b1v = h4_to_f4(Bs[1536 + i]);
        float4 b2v = h4_to_f4(Bs[3072 + i]);
        float4 v;
        v.x = fmaf(h0, a0.x + b0.x, fmaf(h1, a1.x + b1v.x, a2.x + b2v.x));
        v.y = fmaf(h0, a0.y + b0.y, fmaf(h1, a1.y + b1v.y, a2.y + b2v.y));
        v.z = fmaf(h0, a0.z + b0.z, fmaf(h1, a1.z + b1v.z, a2.z + b2v.z));
        v.w = fmaf(h0, a0.w + b0.w, fmaf(h1, a1.w + b1v.w, a2.w + b2v.w));
        v.x = v.x > 0.f ? v.x : 0.01f * v.x;
        v.y = v.y > 0.f ? v.y : 0.01f * v.y;
        v.z = v.z > 0.f ? v.z : 0.01f * v.z;
        v.w = v.w > 0.f ? v.w : 0.01f * v.w;
        int m = i >> 4, c4 = i & 15;
        *(float4*)&al[m * 64 + 4 * (c4 ^ (m & 15))] = v;
    }
    __syncthreads();

    // ---- softmax over batch (8) + msg + vector atomic scatter ----
    if (tid < 192) {
        const int l = tid >> 4, h4 = tid & 15;
        float4 a[8];
        float4 mx = make_float4(-1e30f, -1e30f, -1e30f, -1e30f);
        #pragma unroll
        for (int b = 0; b < 8; b++) {
            int m = b * 12 + l;
            a[b] = *(const float4*)&al[m * 64 + 4 * (h4 ^ (m & 15))];
            mx.x = fmaxf(mx.x, a[b].x); mx.y = fmaxf(mx.y, a[b].y);
            mx.z = fmaxf(mx.z, a[b].z); mx.w = fmaxf(mx.w, a[b].w);
        }
        float4 ssum = make_float4(0.f, 0.f, 0.f, 0.f);
        #pragma unroll
        for (int b = 0; b < 8; b++) {
            a[b].x = fexp2(1.4426950408889634f * (a[b].x - mx.x));
            a[b].y = fexp2(1.4426950408889634f * (a[b].y - mx.y));
            a[b].z = fexp2(1.4426950408889634f * (a[b].z - mx.z));
            a[b].w = fexp2(1.4426950408889634f * (a[b].w - mx.w));
            ssum.x += a[b].x; ssum.y += a[b].y; ssum.z += a[b].z; ssum.w += a[b].w;
        }
        float4 inv = make_float4(frcp(ssum.x), frcp(ssum.y), frcp(ssum.z), frcp(ssum.w));
        float* aggb = g_agg + (size_t)dst * 6144;
        const float4* xj = (const float4*)(g_out1 + (size_t)src * 6144);
        #pragma unroll
        for (int b = 0; b < 8; b++) {
            int m = b * 12 + l;
            float4 sj = xj[m * 16 + h4];
            float4 msg;
            msg.x = a[b].x * inv.x * sj.x;
            msg.y = a[b].y * inv.y * sj.y;
            msg.z = a[b].z * inv.z * sj.z;
            msg.w = a[b].w * inv.w * sj.w;
            asm volatile("red.global.add.v4.f32 [%0], {%1,%2,%3,%4};"
                         :: "l"(aggb + m * 64 + h4 * 4), "f"(msg.x), "f"(msg.y),
                            "f"(msg.z), "f"(msg.w) : "memory");
        }
    }
}

// ---------------------------------------------------------------------------
// GRU2 (unchanged, proven)
// ---------------------------------------------------------------------------
extern "C" __global__ void gru2_kernel(const float* __restrict__ Wih,
                                       const float* __restrict__ Whh,
                                       const float* __restrict__ bih,
                                       const float* __restrict__ bhh,
                                       float* __restrict__ h2_out)
{
    extern __shared__ float sm[];
    float* wT   = sm;
    float* h_sh = sm + 24640;
    float* x_sh = sm + 24640 + 1024;

    const int tid = threadIdx.x;
    const int grp = tid >> 6;
    const int j   = tid & 63;

    for (int idx = tid; idx < 12288; idx += 256) {
        int g = idx >> 6, k = idx & 63;
        int m = g >> 6, jj = g & 63;
        wT[k * 385 + m * 64 + jj]       = Wih[idx];
        wT[k * 385 + 192 + m * 64 + jj] = Whh[idx];
    }

    float br = bih[j], bz = bih[64 + j], bn = bih[128 + j];
    float cr = bhh[j], cz = bhh[64 + j], cn = bhh[128 + j];

    float h[4] = {0.f, 0.f, 0.f, 0.f};
    const int s0 = blockIdx.x * 16 + grp * 4;
    const float* xg = g_agg + (size_t)s0 * 768 + j;

    for (int l = 0; l < LL; l++) {
        float4 xv;
        xv.x = fmaxf(xg[0 * 768 + l * 64], 0.0f);
        xv.y = fmaxf(xg[1 * 768 + l * 64], 0.0f);
        xv.z = fmaxf(xg[2 * 768 + l * 64], 0.0f);
        xv.w = fmaxf(xg[3 * 768 + l * 64], 0.0f);
        *(float4*)&x_sh[grp * 256 + j * 4] = xv;
        *(float4*)&h_sh[grp * 256 + j * 4] = make_float4(h[0], h[1], h[2], h[3]);
        __syncthreads();

        float gr[4], gz[4], gn[4];
        #pragma unroll
        for (int s = 0; s < 4; s++) { gr[s] = br + cr; gz[s] = bz + cz; gn[s] = bn; }
        float ghn[4] = {cn, cn, cn, cn};

        const float* wp = wT + j;
        const float* hp = h_sh + grp * 256;
        const float* xp = x_sh + grp * 256;
        #pragma unroll 2
        for (int k = 0; k < 64; k++) {
            float wi0 = wp[k * 385];
            float wi1 = wp[k * 385 + 64];
            float wi2 = wp[k * 385 + 128];
            float wh0 = wp[k * 385 + 192];
            float wh1 = wp[k * 385 + 256];
            float wh2 = wp[k * 385 + 320];
            float4 xk = *(const float4*)&xp[k * 4];
            float4 hk = *(const float4*)&hp[k * 4];
            gr[0] = fmaf(xk.x, wi0, gr[0]); gz[0] = fmaf(xk.x, wi1, gz[0]); gn[0] = fmaf(xk.x, wi2, gn[0]);
            gr[0] = fmaf(hk.x, wh0, gr[0]); gz[0] = fmaf(hk.x, wh1, gz[0]); ghn[0] = fmaf(hk.x, wh2, ghn[0]);
            gr[1] = fmaf(xk.y, wi0, gr[1]); gz[1] = fmaf(xk.y, wi1, gz[1]); gn[1] = fmaf(xk.y, wi2, gn[1]);
            gr[1] = fmaf(hk.y, wh0, gr[1]); gz[1] = fmaf(hk.y, wh1, gz[1]); ghn[1] = fmaf(hk.y, wh2, ghn[1]);
            gr[2] = fmaf(xk.z, wi0, gr[2]); gz[2] = fmaf(xk.z, wi1, gz[2]); gn[2] = fmaf(xk.z, wi2, gn[2]);
            gr[2] = fmaf(hk.z, wh0, gr[2]); gz[2] = fmaf(hk.z, wh1, gz[2]); ghn[2] = fmaf(hk.z, wh2, ghn[2]);
            gr[3] = fmaf(xk.w, wi0, gr[3]); gz[3] = fmaf(xk.w, wi1, gz[3]); gn[3] = fmaf(xk.w, wi2, gn[3]);
            gr[3] = fmaf(hk.w, wh0, gr[3]); gz[3] = fmaf(hk.w, wh1, gz[3]); ghn[3] = fmaf(hk.w, wh2, ghn[3]);
        }
        #pragma unroll
        for (int s = 0; s < 4; s++) {
            float r = fsig(gr[s]);
            float z = fsig(gz[s]);
            float n = ftanh(fmaf(r, ghn[s], gn[s]));
            h[s] = fmaf(z, h[s] - n, n);
        }
        __syncthreads();
    }
    #pragma unroll
    for (int s = 0; s < 4; s++)
        h2_out[(s0 + s) * 64 + j] = h[s];
}

// ---------------------------------------------------------------------------

static const int GRU1_SMEM = (12352 + 1024 + 384) * 4;
static const int GRU2_SMEM = (24640 + 1024 + 1024) * 4;

extern "C" void kernel_launch(void* const* d_in, const int* in_sizes, int n_in,
                              void* d_out, int out_size)
{
    const float* data     = (const float*)d_in[0];
    const float* features = (const float*)d_in[1];
    const int*   ei       = (const int*)  d_in[2];
    const float* Wih1     = (const float*)d_in[3];
    const float* Whh1     = (const float*)d_in[4];
    const float* bih1     = (const float*)d_in[5];
    const float* bhh1     = (const float*)d_in[6];
    const float* W1       = (const float*)d_in[7];
    const float* b1       = (const float*)d_in[8];
    const float* W2       = (const float*)d_in[9];
    const float* b2       = (const float*)d_in[10];
    const float* W3       = (const float*)d_in[11];
    const float* b3       = (const float*)d_in[12];
    const float* Wih2     = (const float*)d_in[13];
    const float* Whh2     = (const float*)d_in[14];
    const float* bih2     = (const float*)d_in[15];
    const float* bhh2     = (const float*)d_in[16];
    float* out = (float*)d_out;

    cudaFuncSetAttribute(gru1_kernel, cudaFuncAttributeMaxDynamicSharedMemorySize, GRU1_SMEM);
    cudaFuncSetAttribute(gru2_kernel, cudaFuncAttributeMaxDynamicSharedMemorySize, GRU2_SMEM);
    cudaFuncSetAttribute(precomp_kernel, cudaFuncAttributeMaxDynamicSharedMemorySize, PC_SMEM);

    gru1_kernel<<<NSEQ / 16, 256, GRU1_SMEM>>>(data, Wih1, Whh1, bih1, bhh1, out);
    precomp_kernel<<<PRE_GRID, 256, PC_SMEM>>>(W3, b3);
    zero_agg_kernel<<<2048, 256>>>();
    edge_stream_kernel<<<ETOT, 256, ES_SMEM>>>(features, ei, W1, b1, W2, b2);
    gru2_kernel<<<NSEQ / 16, 256, GRU2_SMEM>>>(Wih2, Whh2, bih2, bhh2, out + NSEQ * HH);
}

// round 14
// speedup vs baseline: 2.2716x; 1.0095x over previous
#include <cuda_runtime.h>
#include <cuda_bf16.h>
#include <cuda_fp16.h>
#include <cstdint>
#include <stdint.h>
#include <math.h>

#define NN 2000
#define BB 8
#define LL 12
#define DD 2
#define HH 64
#define EE 16000
#define ETOT 18000
#define NSEQ (NN*BB)                 // 16000
#define OUT1_ELEMS (NSEQ*LL*HH)      // 12,288,000
#define NPB 14                       // nodes per precompute block
#define PRE_GRID ((NN + NPB - 1) / NPB)

__device__ float  g_out1[OUT1_ELEMS];
__device__ __half g_out1h[OUT1_ELEMS];              // fp16 mirror for edge msg
__device__ float  g_agg[OUT1_ELEMS];
__device__ __half g_Yh[(size_t)NN * 6 * 96 * 64];   // 147.5 MB fp16 planes

// ---------------------------------------------------------------------------
// FMA-only fast math (no MUFU)
// ---------------------------------------------------------------------------
__device__ __forceinline__ float fexp2(float y) {
    y = fminf(fmaxf(y, -125.0f), 125.0f);
    float r = __fadd_rn(y, 12582912.0f);
    int   n = __float_as_int(r) - 0x4B400000;
    float f = __fsub_rn(y, __fsub_rn(r, 12582912.0f));
    float u = f * 0.69314718055994531f;
    float p = fmaf(u, 1.3888889e-3f, 8.3333333e-3f);
    p = fmaf(u, p, 4.1666667e-2f);
    p = fmaf(u, p, 1.6666667e-1f);
    p = fmaf(u, p, 0.5f);
    p = fmaf(u, p, 1.0f);
    p = fmaf(u, p, 1.0f);
    return p * __int_as_float((n + 127) << 23);
}
__device__ __forceinline__ float frcp(float x) {
    float r = __int_as_float(0x7EF311C3 - __float_as_int(x));
    r = r * __fmaf_rn(-x, r, 2.0f);
    r = r * __fmaf_rn(-x, r, 2.0f);
    r = r * __fmaf_rn(-x, r, 2.0f);
    return r;
}
__device__ __forceinline__ float fsig(float x) {
    return frcp(1.0f + fexp2(-1.4426950408889634f * x));
}
__device__ __forceinline__ float ftanh(float x) {
    float e = fexp2(2.8853900817779268f * x);
    return fmaf(-2.0f, frcp(1.0f + e), 1.0f);
}

// ---------------------------------------------------------------------------
// mma.sync / ldmatrix helpers (sm_80+ path, legal on sm_103)
// ---------------------------------------------------------------------------
__device__ __forceinline__ uint32_t smem_u32(const void* p) {
    uint32_t a;
    asm("{ .reg .u64 t; cvta.to.shared.u64 t, %1; cvt.u32.u64 %0, t; }"
        : "=r"(a) : "l"(p));
    return a;
}
__device__ __forceinline__ void ldmx4(uint32_t* r, uint32_t addr) {
    asm volatile("ldmatrix.sync.aligned.m8n8.x4.shared.b16 {%0,%1,%2,%3}, [%4];"
                 : "=r"(r[0]), "=r"(r[1]), "=r"(r[2]), "=r"(r[3]) : "r"(addr));
}
__device__ __forceinline__ void mma16816(float* d, const uint32_t* a, const uint32_t* b) {
    asm volatile("mma.sync.aligned.m16n8k16.row.col.f32.bf16.bf16.f32 "
                 "{%0,%1,%2,%3}, {%4,%5,%6,%7}, {%8,%9}, {%0,%1,%2,%3};"
                 : "+f"(d[0]), "+f"(d[1]), "+f"(d[2]), "+f"(d[3])
                 : "r"(a[0]), "r"(a[1]), "r"(a[2]), "r"(a[3]),
                   "r"(b[0]), "r"(b[1]));
}
// tiles with 64 bf16 per row (128 B = 8 x 16B units), unit ^= (row&7)
__device__ __forceinline__ uint32_t tb64(int row, int k) {
    return (uint32_t)(row * 8 + ((k >> 3) ^ (row & 7))) * 16u
         + (uint32_t)(k & 7) * 2u;
}

// ---------------------------------------------------------------------------
// GRU1: 4 seqs/thread (proven) + fp16 mirror store
// ---------------------------------------------------------------------------
extern "C" __global__ void gru1_kernel(const float* __restrict__ data,
                                       const float* __restrict__ Wih,
                                       const float* __restrict__ Whh,
                                       const float* __restrict__ bih,
                                       const float* __restrict__ bhh,
                                       float* __restrict__ h1_out)
{
    extern __shared__ float sm[];
    float* whhT = sm;
    float* h_sh = sm + 12352;
    float* x_sh = sm + 12352 + 1024;

    const int tid = threadIdx.x;
    const int grp = tid >> 6;
    const int j   = tid & 63;

    for (int idx = tid; idx < 12288; idx += 256) {
        int g = idx >> 6, k = idx & 63;
        int m = g >> 6, jj = g & 63;
        whhT[k * 193 + m * 64 + jj] = Whh[idx];
    }
    for (int idx = tid; idx < 384; idx += 256)
        x_sh[idx] = data[(size_t)blockIdx.x * 384 + idx];

    float wr0 = Wih[j * 2],        wr1 = Wih[j * 2 + 1];
    float wz0 = Wih[(64 + j) * 2], wz1 = Wih[(64 + j) * 2 + 1];
    float wn0 = Wih[(128 + j)* 2], wn1 = Wih[(128 + j)* 2 + 1];
    float br = bih[j], bz = bih[64 + j], bn = bih[128 + j];
    float cr = bhh[j], cz = bhh[64 + j], cn = bhh[128 + j];

    float h[4] = {0.f, 0.f, 0.f, 0.f};
    const int s0 = blockIdx.x * 16 + grp * 4;
    float*  outb = g_out1  + (size_t)s0 * 768 + j;
    __half* outh = g_out1h + (size_t)s0 * 768 + j;

    for (int l = 0; l < LL; l++) {
        *(float4*)&h_sh[grp * 256 + j * 4] = make_float4(h[0], h[1], h[2], h[3]);
        __syncthreads();

        float ghr[4], ghz[4], ghn[4];
        #pragma unroll
        for (int s = 0; s < 4; s++) { ghr[s] = cr; ghz[s] = cz; ghn[s] = cn; }

        const float* wp = whhT + j;
        const float* hp = h_sh + grp * 256;
        #pragma unroll 4
        for (int k = 0; k < 64; k++) {
            float w0 = wp[k * 193];
            float w1 = wp[k * 193 + 64];
            float w2 = wp[k * 193 + 128];
            float4 hv = *(const float4*)&hp[k * 4];
            ghr[0] = fmaf(hv.x, w0, ghr[0]); ghz[0] = fmaf(hv.x, w1, ghz[0]); ghn[0] = fmaf(hv.x, w2, ghn[0]);
            ghr[1] = fmaf(hv.y, w0, ghr[1]); ghz[1] = fmaf(hv.y, w1, ghz[1]); ghn[1] = fmaf(hv.y, w2, ghn[1]);
            ghr[2] = fmaf(hv.z, w0, ghr[2]); ghz[2] = fmaf(hv.z, w1, ghz[2]); ghn[2] = fmaf(hv.z, w2, ghn[2]);
            ghr[3] = fmaf(hv.w, w0, ghr[3]); ghz[3] = fmaf(hv.w, w1, ghz[3]); ghn[3] = fmaf(hv.w, w2, ghn[3]);
        }
        #pragma unroll
        for (int s = 0; s < 4; s++) {
            float x0 = x_sh[(grp * 4 + s) * 24 + l * 2];
            float x1 = x_sh[(grp * 4 + s) * 24 + l * 2 + 1];
            float gir = fmaf(x1, wr1, fmaf(x0, wr0, br));
            float giz = fmaf(x1, wz1, fmaf(x0, wz0, bz));
            float gin = fmaf(x1, wn1, fmaf(x0, wn0, bn));
            float r = fsig(gir + ghr[s]);
            float z = fsig(giz + ghz[s]);
            float n = ftanh(fmaf(r, ghn[s], gin));
            h[s] = fmaf(z, h[s] - n, n);
            outb[s * 768 + l * 64] = h[s];
            outh[s * 768 + l * 64] = __float2half(h[s]);
        }
        __syncthreads();
    }
    #pragma unroll
    for (int s = 0; s < 4; s++)
        h1_out[(s0 + s) * 64 + j] = h[s];
}

// ---------------------------------------------------------------------------
extern "C" __global__ void zero_agg_kernel()
{
    float4 z = make_float4(0.f, 0.f, 0.f, 0.f);
    for (int i = blockIdx.x * blockDim.x + threadIdx.x; i < OUT1_ELEMS / 4;
         i += gridDim.x * blockDim.x)
        ((float4*)g_agg)[i] = z;
}

// ---------------------------------------------------------------------------
// Precompute kernel (unchanged, proven): per node n, 6 fp16 planes
// ---------------------------------------------------------------------------
#define PC_BH 0
#define PC_BL 49152
#define PC_XH 98304
#define PC_XL 110592
#define PC_SMEM 122880

extern "C" __global__ void __launch_bounds__(256, 1)
precomp_kernel(const float* __restrict__ W3, const float* __restrict__ b3)
{
    extern __shared__ char smc[];
    const uint32_t sb = smem_u32(smc);
    const int tid = threadIdx.x, wid = tid >> 5, lid = tid & 31;

    for (int i = tid; i < 12288; i += 256) {      // (n, k/2)
        int n = i >> 5, k = (i & 31) * 2;
        int t = n >> 6, h = n & 63;
        int base = (t >= 3) ? 64 : 0;
        int c = t - (t >= 3 ? 3 : 0);
        int m0 = (base + k) * 64 + h;
        int m1 = m0 + 64;
        float v0 = (c == 2) ? b3[m0] : W3[m0 * 2 + c];
        float v1 = (c == 2) ? b3[m1] : W3[m1 * 2 + c];
        __nv_bfloat16 hx = __float2bfloat16(v0);
        __nv_bfloat16 hy = __float2bfloat16(v1);
        __nv_bfloat16 lx = __float2bfloat16(v0 - __bfloat162float(hx));
        __nv_bfloat16 ly = __float2bfloat16(v1 - __bfloat162float(hy));
        uint32_t off = tb64(n, k);
        __nv_bfloat162 th; th.x = hx; th.y = hy;
        __nv_bfloat162 tl; tl.x = lx; tl.y = ly;
        *(__nv_bfloat162*)(smc + PC_BH + off) = th;
        *(__nv_bfloat162*)(smc + PC_BL + off) = tl;
    }
    __syncthreads();

    const int ar  = (lid & 7) + ((lid >> 3) & 1) * 8;
    const int aku = lid >> 4;
    const int br  = (lid & 7) + ((lid >> 4) << 3);
    const int bku = (lid >> 3) & 1;

    const int n0 = blockIdx.x * NPB;
    for (int ni = 0; ni < NPB; ni++) {
        const int node = n0 + ni;
        if (node >= NN) break;

        {
            const float* xp = g_out1 + (size_t)node * 6144;
            for (int i = tid; i < 3072; i += 256) {
                int r = i >> 5, k = (i & 31) * 2;
                float2 v = *(const float2*)(xp + r * 64 + k);
                __nv_bfloat16 hx = __float2bfloat16(v.x);
                __nv_bfloat16 hy = __float2bfloat16(v.y);
                __nv_bfloat16 lx = __float2bfloat16(v.x - __bfloat162float(hx));
                __nv_bfloat16 ly = __float2bfloat16(v.y - __bfloat162float(hy));
                uint32_t off = tb64(r, k);
                __nv_bfloat162 th; th.x = hx; th.y = hy;
                __nv_bfloat162 tl; tl.x = lx; tl.y = ly;
                *(__nv_bfloat162*)(smc + PC_XH + off) = th;
                *(__nv_bfloat162*)(smc + PC_XL + off) = tl;
            }
        }
        __syncthreads();

        if (wid < 6) {
            const int mw = wid >> 1, nw = wid & 1;
            const int arow0 = mw * 32 + ar;
            const int arow1 = arow0 + 16;
            const uint32_t ab0 = (uint32_t)arow0 * 128u, ax0 = (uint32_t)(arow0 & 7);
            const uint32_t ab1 = (uint32_t)arow1 * 128u, ax1 = (uint32_t)(arow1 & 7);

            #pragma unroll
            for (int t = 0; t < 6; t++) {
                float acc[2][4][4];
                #pragma unroll
                for (int a = 0; a < 2; a++)
                    #pragma unroll
                    for (int b = 0; b < 4; b++)
                        #pragma unroll
                        for (int c = 0; c < 4; c++) acc[a][b][c] = 0.0f;

                const int brow0 = t * 64 + nw * 32 + br;
                const int brow1 = brow0 + 16;
                const uint32_t bb0 = (uint32_t)brow0 * 128u, bx0 = (uint32_t)(brow0 & 7);
                const uint32_t bb1 = (uint32_t)brow1 * 128u, bx1 = (uint32_t)(brow1 & 7);

                #pragma unroll
                for (int sp = 0; sp < 3; sp++) {
                    const uint32_t Ab = sb + (sp == 2 ? PC_XL : PC_XH);
                    const uint32_t Bb = sb + (sp == 1 ? PC_BL : PC_BH);
                    #pragma unroll
                    for (int ks = 0; ks < 4; ks++) {
                        const uint32_t kb = (uint32_t)(ks * 2);
                        uint32_t af0[4], af1[4], bf0[4], bf1[4];
                        ldmx4(af0, Ab + ab0 + (((kb + aku) ^ ax0) << 4));
                        ldmx4(af1, Ab + ab1 + (((kb + aku) ^ ax1) << 4));
                        ldmx4(bf0, Bb + bb0 + (((kb + bku) ^ bx0) << 4));
                        ldmx4(bf1, Bb + bb1 + (((kb + bku) ^ bx1) << 4));
                        mma16816(acc[0][0], af0, bf0);
                        mma16816(acc[0][1], af0, bf0 + 2);
                        mma16816(acc[0][2], af0, bf1);
                        mma16816(acc[0][3], af0, bf1 + 2);
                        mma16816(acc[1][0], af1, bf0);
                        mma16816(acc[1][1], af1, bf0 + 2);
                        mma16816(acc[1][2], af1, bf1);
                        mma16816(acc[1][3], af1, bf1 + 2);
                    }
                }
                __half* yp = g_Yh + ((size_t)node * 6 + t) * 6144;
                const int g = lid >> 2, c2 = (lid & 3) * 2;
                #pragma unroll
                for (int mt = 0; mt < 2; mt++) {
                    const int r0 = mw * 32 + mt * 16 + g;
                    const int r1 = r0 + 8;
                    #pragma unroll
                    for (int nt = 0; nt < 4; nt++) {
                        const int c0 = nw * 32 + nt * 8 + c2;
                        *(__half2*)(yp + r0 * 64 + c0) =
                            __floats2half2_rn(acc[mt][nt][0], acc[mt][nt][1]);
                        *(__half2*)(yp + r1 * 64 + c0) =
                            __floats2half2_rn(acc[mt][nt][2], acc[mt][nt][3]);
                    }
                }
            }
        }
        __syncthreads();
    }
}

// ---------------------------------------------------------------------------
// Edge streaming kernel (fp16 planes + fp16 stj)
// ---------------------------------------------------------------------------
#define ES_SMEM (1024 + 24576)

__device__ __forceinline__ float4 h4_to_f4(uint2 u) {
    float2 lo = __half22float2(*(__half2*)&u.x);
    float2 hi = __half22float2(*(__half2*)&u.y);
    float4 r; r.x = lo.x; r.y = lo.y; r.z = hi.x; r.w = hi.y;
    return r;
}

extern "C" __global__ void __launch_bounds__(256)
edge_stream_kernel(const float* __restrict__ features,
                   const int* __restrict__ ei,
                   const float* __restrict__ W1,
                   const float* __restrict__ b1,
                   const float* __restrict__ W2,
                   const float* __restrict__ b2)
{
    extern __shared__ char smc[];
    float* feats = (float*)(smc + 64);
    float* hdn   = (float*)(smc + 576);
    float* hdn2  = (float*)(smc + 640);
    float* al    = (float*)(smc + 1024);

    const int tid = threadIdx.x;
    const int e = blockIdx.x;
    int src, dst;
    if (e < EE) { src = ei[e]; dst = ei[EE + e]; }
    else        { src = dst = e - EE; }

    if (tid < 128)
        feats[tid] = (tid < 64) ? features[dst * 64 + tid]
                                : features[src * 64 + (tid - 64)];
    __syncthreads();

    if (tid < 16) {
        float acc = b1[tid];
        const float* wrow = W1 + tid * 128;
        #pragma unroll 8
        for (int k = 0; k < 128; k++) acc = fmaf(feats[k], wrow[k], acc);
        hdn[tid] = fsig(acc);
    }
    __syncthreads();
    if (tid < 2) {
        float acc = b2[tid];
        const float* wrow = W2 + tid * 16;
        #pragma unroll
        for (int k = 0; k < 16; k++) acc = fmaf(hdn[k], wrow[k], acc);
        hdn2[tid] = fsig(acc);
    }
    __syncthreads();

    const float h0 = hdn2[0], h1 = hdn2[1];
    const uint2* Ad = (const uint2*)(g_Yh + (size_t)dst * 36864);          // planes 0..2
    const uint2* Bs = (const uint2*)(g_Yh + (size_t)src * 36864 + 18432);  // planes 3..5

    #pragma unroll 2
    for (int i = tid; i < 1536; i += 256) {
        float4 a0 = h4_to_f4(Ad[i]);
        float4 a1 = h4_to_f4(Ad[1536 + i]);
        float4 a2 = h4_to_f4(Ad[3072 + i]);
        float4 b0 = h4_to_f4(Bs[i]);
        float4 b1v = h4_to_f4(Bs[1536 + i]);
        float4 b2v = h4_to_f4(Bs[3072 + i]);
        float4 v;
        v.x = fmaf(h0, a0.x + b0.x, fmaf(h1, a1.x + b1v.x, a2.x + b2v.x));
        v.y = fmaf(h0, a0.y + b0.y, fmaf(h1, a1.y + b1v.y, a2.y + b2v.y));
        v.z = fmaf(h0, a0.z + b0.z, fmaf(h1, a1.z + b1v.z, a2.z + b2v.z));
        v.w = fmaf(h0, a0.w + b0.w, fmaf(h1, a1.w + b1v.w, a2.w + b2v.w));
        v.x = v.x > 0.f ? v.x : 0.01f * v.x;
        v.y = v.y > 0.f ? v.y : 0.01f * v.y;
        v.z = v.z > 0.f ? v.z : 0.01f * v.z;
        v.w = v.w > 0.f ? v.w : 0.01f * v.w;
        int m = i >> 4, c4 = i & 15;
        *(float4*)&al[m * 64 + 4 * (c4 ^ (m & 15))] = v;
    }
    __syncthreads();

    // ---- softmax over batch (8) + msg + vector atomic scatter ----
    if (tid < 192) {
        const int l = tid >> 4, h4 = tid & 15;
        float4 a[8];
        float4 mx = make_float4(-1e30f, -1e30f, -1e30f, -1e30f);
        #pragma unroll
        for (int b = 0; b < 8; b++) {
            int m = b * 12 + l;
            a[b] = *(const float4*)&al[m * 64 + 4 * (h4 ^ (m & 15))];
            mx.x = fmaxf(mx.x, a[b].x); mx.y = fmaxf(mx.y, a[b].y);
            mx.z = fmaxf(mx.z, a[b].z); mx.w = fmaxf(mx.w, a[b].w);
        }
        float4 ssum = make_float4(0.f, 0.f, 0.f, 0.f);
        #pragma unroll
        for (int b = 0; b < 8; b++) {
            a[b].x = fexp2(1.4426950408889634f * (a[b].x - mx.x));
            a[b].y = fexp2(1.4426950408889634f * (a[b].y - mx.y));
            a[b].z = fexp2(1.4426950408889634f * (a[b].z - mx.z));
            a[b].w = fexp2(1.4426950408889634f * (a[b].w - mx.w));
            ssum.x += a[b].x; ssum.y += a[b].y; ssum.z += a[b].z; ssum.w += a[b].w;
        }
        float4 inv = make_float4(frcp(ssum.x), frcp(ssum.y), frcp(ssum.z), frcp(ssum.w));
        float* aggb = g_agg + (size_t)dst * 6144;
        const uint2* xj = (const uint2*)(g_out1h + (size_t)src * 6144);
        #pragma unroll
        for (int b = 0; b < 8; b++) {
            int m = b * 12 + l;
            float4 sj = h4_to_f4(xj[m * 16 + h4]);
            float4 msg;
            msg.x = a[b].x * inv.x * sj.x;
            msg.y = a[b].y * inv.y * sj.y;
            msg.z = a[b].z * inv.z * sj.z;
            msg.w = a[b].w * inv.w * sj.w;
            asm volatile("red.global.add.v4.f32 [%0], {%1,%2,%3,%4};"
                         :: "l"(aggb + m * 64 + h4 * 4), "f"(msg.x), "f"(msg.y),
                            "f"(msg.z), "f"(msg.w) : "memory");
        }
    }
}

// ---------------------------------------------------------------------------
// GRU2: 8 sequences/thread, 32 seqs/block, 500 blocks.
// smem: wT 24640 @0, h_sh 2048 @24640, x_sh 2048 @26688  (114,944 B)
// ---------------------------------------------------------------------------
extern "C" __global__ void __launch_bounds__(256)
gru2_kernel(const float* __restrict__ Wih,
            const float* __restrict__ Whh,
            const float* __restrict__ bih,
            const float* __restrict__ bhh,
            float* __restrict__ h2_out)
{
    extern __shared__ float sm[];
    float* wT   = sm;                     // 64 * 385
    float* h_sh = sm + 24640;             // 4 grp * 64 k * 8 s
    float* x_sh = sm + 24640 + 2048;      // same

    const int tid = threadIdx.x;
    const int grp = tid >> 6;
    const int j   = tid & 63;

    for (int idx = tid; idx < 12288; idx += 256) {
        int g = idx >> 6, k = idx & 63;
        int m = g >> 6, jj = g & 63;
        wT[k * 385 + m * 64 + jj]       = Wih[idx];
        wT[k * 385 + 192 + m * 64 + jj] = Whh[idx];
    }

    float br = bih[j], bz = bih[64 + j], bn = bih[128 + j];
    float cr = bhh[j], cz = bhh[64 + j], cn = bhh[128 + j];

    float h[8] = {0.f, 0.f, 0.f, 0.f, 0.f, 0.f, 0.f, 0.f};
    const int s0 = blockIdx.x * 32 + grp * 8;
    const float* xg = g_agg + (size_t)s0 * 768 + j;

    for (int l = 0; l < LL; l++) {
        // stage x (relu) and h transposed [k][8]
        float xv[8];
        #pragma unroll
        for (int s = 0; s < 8; s++)
            xv[s] = fmaxf(xg[s * 768 + l * 64], 0.0f);
        *(float4*)&x_sh[grp * 512 + j * 8]     = make_float4(xv[0], xv[1], xv[2], xv[3]);
        *(float4*)&x_sh[grp * 512 + j * 8 + 4] = make_float4(xv[4], xv[5], xv[6], xv[7]);
        *(float4*)&h_sh[grp * 512 + j * 8]     = make_float4(h[0], h[1], h[2], h[3]);
        *(float4*)&h_sh[grp * 512 + j * 8 + 4] = make_float4(h[4], h[5], h[6], h[7]);
        __syncthreads();

        float gr[8], gz[8], gn[8], ghn[8];
        #pragma unroll
        for (int s = 0; s < 8; s++) {
            gr[s] = br + cr; gz[s] = bz + cz; gn[s] = bn; ghn[s] = cn;
        }

        const float* wp = wT + j;
        const float* hp = h_sh + grp * 512;
        const float* xp = x_sh + grp * 512;
        #pragma unroll 2
        for (int k = 0; k < 64; k++) {
            float wi0 = wp[k * 385];
            float wi1 = wp[k * 385 + 64];
            float wi2 = wp[k * 385 + 128];
            float wh0 = wp[k * 385 + 192];
            float wh1 = wp[k * 385 + 256];
            float wh2 = wp[k * 385 + 320];
            float4 xk0 = *(const float4*)&xp[k * 8];
            float4 xk1 = *(const float4*)&xp[k * 8 + 4];
            float4 hk0 = *(const float4*)&hp[k * 8];
            float4 hk1 = *(const float4*)&hp[k * 8 + 4];
            const float xs[8] = {xk0.x, xk0.y, xk0.z, xk0.w, xk1.x, xk1.y, xk1.z, xk1.w};
            const float hs[8] = {hk0.x, hk0.y, hk0.z, hk0.w, hk1.x, hk1.y, hk1.z, hk1.w};
            #pragma unroll
            for (int s = 0; s < 8; s++) {
                gr[s]  = fmaf(xs[s], wi0, gr[s]);
                gz[s]  = fmaf(xs[s], wi1, gz[s]);
                gn[s]  = fmaf(xs[s], wi2, gn[s]);
                gr[s]  = fmaf(hs[s], wh0, gr[s]);
                gz[s]  = fmaf(hs[s], wh1, gz[s]);
                ghn[s] = fmaf(hs[s], wh2, ghn[s]);
            }
        }
        #pragma unroll
        for (int s = 0; s < 8; s++) {
            float r = fsig(gr[s]);
            float z = fsig(gz[s]);
            float n = ftanh(fmaf(r, ghn[s], gn[s]));
            h[s] = fmaf(z, h[s] - n, n);
        }
        __syncthreads();
    }
    #pragma unroll
    for (int s = 0; s < 8; s++)
        h2_out[(s0 + s) * 64 + j] = h[s];
}

// ---------------------------------------------------------------------------

static const int GRU1_SMEM = (12352 + 1024 + 384) * 4;
static const int GRU2_SMEM = (24640 + 2048 + 2048) * 4;   // 114,944 B

extern "C" void kernel_launch(void* const* d_in, const int* in_sizes, int n_in,
                              void* d_out, int out_size)
{
    const float* data     = (const float*)d_in[0];
    const float* features = (const float*)d_in[1];
    const int*   ei       = (const int*)  d_in[2];
    const float* Wih1     = (const float*)d_in[3];
    const float* Whh1     = (const float*)d_in[4];
    const float* bih1     = (const float*)d_in[5];
    const float* bhh1     = (const float*)d_in[6];
    const float* W1       = (const float*)d_in[7];
    const float* b1       = (const float*)d_in[8];
    const float* W2       = (const float*)d_in[9];
    const float* b2       = (const float*)d_in[10];
    const float* W3       = (const float*)d_in[11];
    const float* b3       = (const float*)d_in[12];
    const float* Wih2     = (const float*)d_in[13];
    const float* Whh2     = (const float*)d_in[14];
    const float* bih2     = (const float*)d_in[15];
    const float* bhh2     = (const float*)d_in[16];
    float* out = (float*)d_out;

    cudaFuncSetAttribute(gru1_kernel, cudaFuncAttributeMaxDynamicSharedMemorySize, GRU1_SMEM);
    cudaFuncSetAttribute(gru2_kernel, cudaFuncAttributeMaxDynamicSharedMemorySize, GRU2_SMEM);
    cudaFuncSetAttribute(precomp_kernel, cudaFuncAttributeMaxDynamicSharedMemorySize, PC_SMEM);

    gru1_kernel<<<NSEQ / 16, 256, GRU1_SMEM>>>(data, Wih1, Whh1, bih1, bhh1, out);
    precomp_kernel<<<PRE_GRID, 256, PC_SMEM>>>(W3, b3);
    zero_agg_kernel<<<2048, 256>>>();
    edge_stream_kernel<<<ETOT, 256, ES_SMEM>>>(features, ei, W1, b1, W2, b2);
    gru2_kernel<<<NSEQ / 32, 256, GRU2_SMEM>>>(Wih2, Whh2, bih2, bhh2, out + NSEQ * HH);
}